// round 4
// baseline (speedup 1.0000x reference)
#include <cuda_runtime.h>

#define NB   8
#define HH   32
#define WW   32
#define HW   1024
#define NHD  8
#define DKH_ 16

// scratch (no cudaMalloc allowed)
__device__ float g_kqv[(size_t)NB * 384 * HW];   // (N, 384, HW): k[0:128], q[128:256] (scaled), v[256:384]
__device__ float g_attn[(size_t)NB * 128 * HW];  // flat (N, NH, HW, DVH) == (N,128,HW) after torch-style reshape

// ---------------------------------------------------------------------------
// Generic implicit-im2col SGEMM conv. Tile: 64 Cout x 64 pixels, BK=16,
// 256 threads, 4x4 microtile. Exact tiling (all dims divide).
// ---------------------------------------------------------------------------
template <int KH, int KW, int PAD>
__global__ __launch_bounds__(256) void conv_gemm_kernel(
    const float* __restrict__ x, const float* __restrict__ w,
    const float* __restrict__ bias, float* __restrict__ out,
    int Cin, int oss /*out elems per sample*/, int cho /*out ch offset*/,
    int qlo, int qhi, float qscale)
{
    const int Ktot = Cin * KH * KW;
    __shared__ float As[16][64];
    __shared__ float Bs[16][64];

    const int tid = threadIdx.x;
    const int p0 = blockIdx.x * 64;
    const int m0 = blockIdx.y * 64;
    const int n  = blockIdx.z;
    const int tm = tid >> 4, tn = tid & 15;

    float acc[4][4];
#pragma unroll
    for (int i = 0; i < 4; i++)
#pragma unroll
        for (int j = 0; j < 4; j++) acc[i][j] = 0.f;

    for (int k0 = 0; k0 < Ktot; k0 += 16) {
        __syncthreads();
        {   // A: weights (Cout, Ktot) contiguous in k -> float4 loads
            int m  = tid >> 2;
            int kq = (tid & 3) << 2;
            float4 av = *(const float4*)(w + (size_t)(m0 + m) * Ktot + k0 + kq);
            As[kq + 0][m] = av.x; As[kq + 1][m] = av.y;
            As[kq + 2][m] = av.z; As[kq + 3][m] = av.w;
        }
#pragma unroll
        for (int r = 0; r < 4; r++) {  // B: implicit im2col
            int e  = tid + r * 256;
            int kk = e >> 6;
            int p  = e & 63;
            int kg = k0 + kk;
            float val;
            if (KH == 1 && KW == 1) {
                val = x[((size_t)n * Cin + kg) * HW + p0 + p];
            } else {
                int ci = kg / (KH * KW);
                int rr = kg - ci * (KH * KW);
                int kh = rr / KW;
                int kw = rr - kh * KW;
                int P  = p0 + p;
                int ph = P >> 5, pw = P & 31;
                int hh = ph + kh - PAD, wp = pw + kw - PAD;
                val = (hh >= 0 && hh < HH && wp >= 0 && wp < WW)
                          ? x[((size_t)n * Cin + ci) * HW + hh * WW + wp]
                          : 0.f;
            }
            Bs[kk][p] = val;
        }
        __syncthreads();
#pragma unroll
        for (int kk = 0; kk < 16; kk++) {
            float ar[4], br[4];
            *(float4*)ar = *(const float4*)&As[kk][tm * 4];
            *(float4*)br = *(const float4*)&Bs[kk][tn * 4];
#pragma unroll
            for (int i = 0; i < 4; i++)
#pragma unroll
                for (int j = 0; j < 4; j++)
                    acc[i][j] = fmaf(ar[i], br[j], acc[i][j]);
        }
    }

#pragma unroll
    for (int i = 0; i < 4; i++) {
        int co   = m0 + tm * 4 + i;
        float bb = bias[co];
        float sc = (co >= qlo && co < qhi) ? qscale : 1.f;
        float4 v;
        v.x = (acc[i][0] + bb) * sc;
        v.y = (acc[i][1] + bb) * sc;
        v.z = (acc[i][2] + bb) * sc;
        v.w = (acc[i][3] + bb) * sc;
        *(float4*)(out + (size_t)n * oss + (size_t)(cho + co) * HW + p0 + tn * 4) = v;
    }
}

// ---------------------------------------------------------------------------
// Fused relative-position attention, flash style.
// bias(m=(x,y), n=(i,j)) = q_m . key_rel_w[j-y+31] + q_m . key_rel_h[i-x+31]
// One thread per query row m (128 rows/block), K/V streamed in 64-col chunks.
// rel biases precomputed transposed in SMEM -> broadcast-conflict-free reads.
// Writes flat (N, NH, HW, DVH) buffer (== torch raw reshape to (N,128,H,W)).
// ---------------------------------------------------------------------------
__global__ __launch_bounds__(128) void attn_kernel(
    const float* __restrict__ krw, const float* __restrict__ krh)
{
    __shared__ float srw[32][128];  // [j][tid]
    __shared__ float srh[32][128];  // [i][tid]
    __shared__ float Ks[16][64];
    __shared__ float Vs[16][64];

    const int tid = threadIdx.x;
    const int b = blockIdx.z, h = blockIdx.y;
    const int m = blockIdx.x * 128 + tid;

    const float* kb = g_kqv + ((size_t)b * 384 + h * DKH_) * HW;
    const float* qb = g_kqv + ((size_t)b * 384 + 128 + h * DKH_) * HW;
    const float* vb = g_kqv + ((size_t)b * 384 + 256 + h * DKH_) * HW;

    float q[16];
#pragma unroll
    for (int d = 0; d < 16; d++) q[d] = qb[(size_t)d * HW + m];

    const int xr = m >> 5, yc = m & 31;
#pragma unroll 1
    for (int j = 0; j < 32; j++) {
        const float* kw_ = krw + (j + 31 - yc) * DKH_;
        const float* kh_ = krh + (j + 31 - xr) * DKH_;
        float s1 = 0.f, s2 = 0.f;
#pragma unroll
        for (int d = 0; d < 16; d++) {
            s1 = fmaf(q[d], kw_[d], s1);
            s2 = fmaf(q[d], kh_[d], s2);
        }
        srw[j][tid] = s1;
        srh[j][tid] = s2;
    }

    float mrun = -1e30f, l = 0.f;
    float acc[16];
#pragma unroll
    for (int d = 0; d < 16; d++) acc[d] = 0.f;

    for (int n0 = 0; n0 < HW; n0 += 64) {
        __syncthreads();
#pragma unroll
        for (int r = 0; r < 8; r++) {
            int e = tid + r * 128;
            int d = e >> 6, nn = e & 63;
            Ks[d][nn] = kb[(size_t)d * HW + n0 + nn];
            Vs[d][nn] = vb[(size_t)d * HW + n0 + nn];
        }
        __syncthreads();

#pragma unroll 1
        for (int ii = 0; ii < 2; ii++) {
            const int i = (n0 >> 5) + ii;
            const float rh = srh[i][tid];
            float sbuf[32];
            float cmax = -1e30f;
#pragma unroll
            for (int j = 0; j < 32; j++) {
                float s = srw[j][tid] + rh;
#pragma unroll
                for (int d = 0; d < 16; d++)
                    s = fmaf(q[d], Ks[d][ii * 32 + j], s);
                sbuf[j] = s;
                cmax = fmaxf(cmax, s);
            }
            float newm = fmaxf(mrun, cmax);
            float corr = exp2f((mrun - newm) * 1.44269504f);
            l *= corr;
#pragma unroll
            for (int d = 0; d < 16; d++) acc[d] *= corr;
#pragma unroll
            for (int j = 0; j < 32; j++) {
                float p = exp2f((sbuf[j] - newm) * 1.44269504f);
                l += p;
#pragma unroll
                for (int d = 0; d < 16; d++)
                    acc[d] = fmaf(p, Vs[d][ii * 32 + j], acc[d]);
            }
            mrun = newm;
        }
    }

    const float inv = 1.f / l;
    float* o = g_attn + (((size_t)b * NHD + h) * HW + m) * 16;
#pragma unroll
    for (int t = 0; t < 4; t++) {
        float4 v;
        v.x = acc[t * 4 + 0] * inv;
        v.y = acc[t * 4 + 1] * inv;
        v.z = acc[t * 4 + 2] * inv;
        v.w = acc[t * 4 + 3] * inv;
        *(float4*)(o + t * 4) = v;
    }
}

// ---------------------------------------------------------------------------
extern "C" void kernel_launch(void* const* d_in, const int* in_sizes, int n_in,
                              void* d_out, int out_size)
{
    const float* x      = (const float*)d_in[0];
    const float* w_out  = (const float*)d_in[1];
    const float* b_out  = (const float*)d_in[2];
    const float* w_kqv  = (const float*)d_in[3];
    const float* b_kqv  = (const float*)d_in[4];
    const float* w_attn = (const float*)d_in[5];
    const float* b_attn = (const float*)d_in[6];
    const float* krw    = (const float*)d_in[7];
    const float* krh    = (const float*)d_in[8];
    float* out = (float*)d_out;

    float *kqv_ptr = nullptr, *attn_ptr = nullptr;
    cudaGetSymbolAddress((void**)&kqv_ptr, g_kqv);
    cudaGetSymbolAddress((void**)&attn_ptr, g_attn);

    dim3 blk(256);
    // conv3x3 -> out channels [0,384)
    conv_gemm_kernel<3, 3, 1><<<dim3(16, 6, 8), blk>>>(
        x, w_out, b_out, out, 256, 512 * HW, 0, 0, 0, 1.f);
    // 1x1 kqv (384 ch) -> g_kqv ; q channels [128,256) scaled by DKH^-0.5 = 0.25
    conv_gemm_kernel<1, 1, 0><<<dim3(16, 6, 8), blk>>>(
        x, w_kqv, b_kqv, kqv_ptr, 256, 384 * HW, 0, 128, 256, 0.25f);
    // fused rel-pos attention -> g_attn
    attn_kernel<<<dim3(8, 8, 8), 128>>>(krw, krh);
    // 1x1 attn projection -> out channels [384,512)
    conv_gemm_kernel<1, 1, 0><<<dim3(16, 2, 8), blk>>>(
        attn_ptr, w_attn, b_attn, out, 128, 512 * HW, 384, 0, 0, 1.f);
}

// round 6
// speedup vs baseline: 1.2323x; 1.2323x over previous
#include <cuda_runtime.h>
#include <cstdint>

#define NB   8
#define HH   32
#define WW   32
#define HW   1024
#define NHD  8
#define DKH_ 16

// scratch (no cudaMalloc allowed)
__device__ float g_kqv[(size_t)NB * 384 * HW];   // (N,384,HW): k[0:128], q[128:256] (scaled), v[256:384]
__device__ float g_attn[(size_t)NB * 128 * HW];  // flat (N,NH,HW,DVH) == raw-reshape (N,128,HW)

// ---------------------------------------------------------------------------
// helpers
// ---------------------------------------------------------------------------
__device__ __forceinline__ float tf32hi(float x) {
    uint32_t u;
    asm("cvt.rna.tf32.f32 %0, %1;" : "=r"(u) : "f"(x));
    return __uint_as_float(u);
}

__device__ __forceinline__ void mma8(float4& d, const float* a, const float* b) {
    asm volatile(
        "mma.sync.aligned.m16n8k8.row.col.f32.tf32.tf32.f32 "
        "{%0,%1,%2,%3},{%4,%5,%6,%7},{%8,%9},{%0,%1,%2,%3};"
        : "+f"(d.x), "+f"(d.y), "+f"(d.z), "+f"(d.w)
        : "r"(__float_as_uint(a[0])), "r"(__float_as_uint(a[1])),
          "r"(__float_as_uint(a[2])), "r"(__float_as_uint(a[3])),
          "r"(__float_as_uint(b[0])), "r"(__float_as_uint(b[1])));
}

// ---------------------------------------------------------------------------
// Implicit-im2col GEMM conv on tensor pipe: tf32 mma with 3xTF32 split
// (full fp32-grade precision). Block tile 64(Cout) x 128(pix), BK=16,
// 8 warps in 2x4, warp tile 32x32 (2x4 m16n8 tiles), 2 k8-steps per chunk.
// ---------------------------------------------------------------------------
template <int KH, int KW, int PAD>
__global__ __launch_bounds__(256, 2) void conv_mma_kernel(
    const float* __restrict__ x, const float* __restrict__ w,
    const float* __restrict__ bias, float* __restrict__ out,
    int Cin, int oss, int cho, int qlo, int qhi, float qscale)
{
    const int Ktot = Cin * KH * KW;
    __shared__ float A_hi[64][20], A_lo[64][20];     // [m][k], pad->conflict-free
    __shared__ float B_hi[16][136], B_lo[16][136];   // [k][n], pad->conflict-free

    const int tid  = threadIdx.x;
    const int lane = tid & 31;
    const int warp = tid >> 5;
    const int wm   = warp >> 2;            // 0..1
    const int wn   = warp & 3;             // 0..3
    const int gid  = lane >> 2;            // 0..7
    const int tig  = lane & 3;             // 0..3

    const int p0 = blockIdx.x * 128;
    const int m0 = blockIdx.y * 64;
    const int n  = blockIdx.z;

    float4 acc[2][4];
#pragma unroll
    for (int i = 0; i < 2; i++)
#pragma unroll
        for (int j = 0; j < 4; j++) acc[i][j] = make_float4(0.f, 0.f, 0.f, 0.f);

    for (int k0 = 0; k0 < Ktot; k0 += 16) {
        __syncthreads();
        {   // A: weights (Cout, Ktot), contiguous in k -> float4 loads, split hi/lo
            int m  = tid >> 2;
            int k4 = (tid & 3) << 2;
            float4 av = *(const float4*)(w + (size_t)(m0 + m) * Ktot + k0 + k4);
            float4 hv, lv;
            hv.x = tf32hi(av.x); lv.x = av.x - hv.x;
            hv.y = tf32hi(av.y); lv.y = av.y - hv.y;
            hv.z = tf32hi(av.z); lv.z = av.z - hv.z;
            hv.w = tf32hi(av.w); lv.w = av.w - hv.w;
            *(float4*)&A_hi[m][k4] = hv;
            *(float4*)&A_lo[m][k4] = lv;
        }
#pragma unroll
        for (int r = 0; r < 8; r++) {   // B: implicit im2col, split hi/lo
            int e  = tid + r * 256;
            int kk = e >> 7;
            int p  = e & 127;
            int kg = k0 + kk;
            float val;
            if (KH == 1 && KW == 1) {
                val = x[((size_t)n * Cin + kg) * HW + p0 + p];
            } else {
                int ci = kg / (KH * KW);
                int rr = kg - ci * (KH * KW);
                int kh = rr / KW;
                int kw = rr - kh * KW;
                int P  = p0 + p;
                int ph = P >> 5, pw = P & 31;
                int hh = ph + kh - PAD, wp = pw + kw - PAD;
                val = (hh >= 0 && hh < HH && wp >= 0 && wp < WW)
                          ? x[((size_t)n * Cin + ci) * HW + hh * WW + wp]
                          : 0.f;
            }
            float hv = tf32hi(val);
            B_hi[kk][p] = hv;
            B_lo[kk][p] = val - hv;
        }
        __syncthreads();

#pragma unroll
        for (int ks = 0; ks < 2; ks++) {
            float a_hi[2][4], a_lo[2][4], b_hi[4][2], b_lo[4][2];
#pragma unroll
            for (int mt = 0; mt < 2; mt++) {
                int rb = wm * 32 + mt * 16;
                a_hi[mt][0] = A_hi[rb + gid][ks * 8 + tig];
                a_hi[mt][1] = A_hi[rb + gid + 8][ks * 8 + tig];
                a_hi[mt][2] = A_hi[rb + gid][ks * 8 + tig + 4];
                a_hi[mt][3] = A_hi[rb + gid + 8][ks * 8 + tig + 4];
                a_lo[mt][0] = A_lo[rb + gid][ks * 8 + tig];
                a_lo[mt][1] = A_lo[rb + gid + 8][ks * 8 + tig];
                a_lo[mt][2] = A_lo[rb + gid][ks * 8 + tig + 4];
                a_lo[mt][3] = A_lo[rb + gid + 8][ks * 8 + tig + 4];
            }
#pragma unroll
            for (int nt = 0; nt < 4; nt++) {
                int cb = wn * 32 + nt * 8;
                b_hi[nt][0] = B_hi[ks * 8 + tig][cb + gid];
                b_hi[nt][1] = B_hi[ks * 8 + tig + 4][cb + gid];
                b_lo[nt][0] = B_lo[ks * 8 + tig][cb + gid];
                b_lo[nt][1] = B_lo[ks * 8 + tig + 4][cb + gid];
            }
#pragma unroll
            for (int mt = 0; mt < 2; mt++)
#pragma unroll
                for (int nt = 0; nt < 4; nt++) {
                    mma8(acc[mt][nt], a_hi[mt], b_hi[nt]);
                    mma8(acc[mt][nt], a_lo[mt], b_hi[nt]);
                    mma8(acc[mt][nt], a_hi[mt], b_lo[nt]);
                }
        }
    }

#pragma unroll
    for (int mt = 0; mt < 2; mt++) {
        int r0 = m0 + wm * 32 + mt * 16 + gid;
        int r1 = r0 + 8;
        float b0 = bias[r0], b1 = bias[r1];
        float s0 = (r0 >= qlo && r0 < qhi) ? qscale : 1.f;
        float s1 = (r1 >= qlo && r1 < qhi) ? qscale : 1.f;
#pragma unroll
        for (int nt = 0; nt < 4; nt++) {
            int c0 = p0 + wn * 32 + nt * 8 + tig * 2;
            float2 v0, v1;
            v0.x = (acc[mt][nt].x + b0) * s0;
            v0.y = (acc[mt][nt].y + b0) * s0;
            v1.x = (acc[mt][nt].z + b1) * s1;
            v1.y = (acc[mt][nt].w + b1) * s1;
            *(float2*)(out + (size_t)n * oss + (size_t)(cho + r0) * HW + c0) = v0;
            *(float2*)(out + (size_t)n * oss + (size_t)(cho + r1) * HW + c0) = v1;
        }
    }
}

// ---------------------------------------------------------------------------
// Fused relative-position attention, flash style.
// bias(m=(x,y), n=(i,j)) = q_m . key_rel_w[j-y+31] + q_m . key_rel_h[i-x+31]
// One thread per query row m; K/V streamed in 64-col chunks; inner loops
// vectorized with float4 broadcast LDS (1 LDS per 4 FMA) -> FFMA-bound.
// ---------------------------------------------------------------------------
__global__ __launch_bounds__(128) void attn_kernel(
    const float* __restrict__ krw, const float* __restrict__ krh)
{
    __shared__ float srw[32][128];  // [j][tid]
    __shared__ float srh[32][128];  // [i][tid]
    __shared__ float Ks[16][64];
    __shared__ float Vs[16][64];

    const int tid = threadIdx.x;
    const int b = blockIdx.z, h = blockIdx.y;
    const int m = blockIdx.x * 128 + tid;

    const float* kb = g_kqv + ((size_t)b * 384 + h * DKH_) * HW;
    const float* qb = g_kqv + ((size_t)b * 384 + 128 + h * DKH_) * HW;
    const float* vb = g_kqv + ((size_t)b * 384 + 256 + h * DKH_) * HW;

    float q[16];
#pragma unroll
    for (int d = 0; d < 16; d++) q[d] = qb[(size_t)d * HW + m];

    const int xr = m >> 5, yc = m & 31;
#pragma unroll 1
    for (int j = 0; j < 32; j++) {
        const float* kw_ = krw + (j + 31 - yc) * DKH_;
        const float* kh_ = krh + (j + 31 - xr) * DKH_;
        float s1 = 0.f, s2 = 0.f;
#pragma unroll
        for (int d = 0; d < 16; d++) {
            s1 = fmaf(q[d], kw_[d], s1);
            s2 = fmaf(q[d], kh_[d], s2);
        }
        srw[j][tid] = s1;
        srh[j][tid] = s2;
    }

    float mrun = -1e30f, l = 0.f;
    float acc[16];
#pragma unroll
    for (int d = 0; d < 16; d++) acc[d] = 0.f;

    for (int n0 = 0; n0 < HW; n0 += 64) {
        __syncthreads();
#pragma unroll
        for (int r = 0; r < 8; r++) {
            int e = tid + r * 128;
            int d = e >> 6, nn = e & 63;
            Ks[d][nn] = kb[(size_t)d * HW + n0 + nn];
            Vs[d][nn] = vb[(size_t)d * HW + n0 + nn];
        }
        __syncthreads();

#pragma unroll 1
        for (int ii = 0; ii < 2; ii++) {
            const int i = (n0 >> 5) + ii;
            const float rh = srh[i][tid];
            float sbuf[32];
#pragma unroll
            for (int j = 0; j < 32; j++) sbuf[j] = srw[j][tid] + rh;

            // QK: float4 broadcast along j
#pragma unroll
            for (int d = 0; d < 16; d++) {
                const float qd = q[d];
#pragma unroll
                for (int jb = 0; jb < 8; jb++) {
                    float4 k4 = *(const float4*)&Ks[d][ii * 32 + jb * 4];
                    sbuf[jb * 4 + 0] = fmaf(qd, k4.x, sbuf[jb * 4 + 0]);
                    sbuf[jb * 4 + 1] = fmaf(qd, k4.y, sbuf[jb * 4 + 1]);
                    sbuf[jb * 4 + 2] = fmaf(qd, k4.z, sbuf[jb * 4 + 2]);
                    sbuf[jb * 4 + 3] = fmaf(qd, k4.w, sbuf[jb * 4 + 3]);
                }
            }

            float cmax = -1e30f;
#pragma unroll
            for (int j = 0; j < 32; j++) cmax = fmaxf(cmax, sbuf[j]);
            float newm = fmaxf(mrun, cmax);
            float corr = exp2f((mrun - newm) * 1.44269504f);
            l *= corr;
#pragma unroll
            for (int d = 0; d < 16; d++) acc[d] *= corr;

#pragma unroll
            for (int j = 0; j < 32; j++) {
                float p = exp2f((sbuf[j] - newm) * 1.44269504f);
                l += p;
                sbuf[j] = p;
            }

            // PV: float4 broadcast along j
#pragma unroll
            for (int d = 0; d < 16; d++) {
                float a = acc[d];
#pragma unroll
                for (int jb = 0; jb < 8; jb++) {
                    float4 v4 = *(const float4*)&Vs[d][ii * 32 + jb * 4];
                    a = fmaf(sbuf[jb * 4 + 0], v4.x, a);
                    a = fmaf(sbuf[jb * 4 + 1], v4.y, a);
                    a = fmaf(sbuf[jb * 4 + 2], v4.z, a);
                    a = fmaf(sbuf[jb * 4 + 3], v4.w, a);
                }
                acc[d] = a;
            }
            mrun = newm;
        }
    }

    const float inv = 1.f / l;
    float* o = g_attn + (((size_t)b * NHD + h) * HW + m) * 16;
#pragma unroll
    for (int t = 0; t < 4; t++) {
        float4 v;
        v.x = acc[t * 4 + 0] * inv;
        v.y = acc[t * 4 + 1] * inv;
        v.z = acc[t * 4 + 2] * inv;
        v.w = acc[t * 4 + 3] * inv;
        *(float4*)(o + t * 4) = v;
    }
}

// ---------------------------------------------------------------------------
extern "C" void kernel_launch(void* const* d_in, const int* in_sizes, int n_in,
                              void* d_out, int out_size)
{
    const float* x      = (const float*)d_in[0];
    const float* w_out  = (const float*)d_in[1];
    const float* b_out  = (const float*)d_in[2];
    const float* w_kqv  = (const float*)d_in[3];
    const float* b_kqv  = (const float*)d_in[4];
    const float* w_attn = (const float*)d_in[5];
    const float* b_attn = (const float*)d_in[6];
    const float* krw    = (const float*)d_in[7];
    const float* krh    = (const float*)d_in[8];
    float* out = (float*)d_out;

    float *kqv_ptr = nullptr, *attn_ptr = nullptr;
    cudaGetSymbolAddress((void**)&kqv_ptr, g_kqv);
    cudaGetSymbolAddress((void**)&attn_ptr, g_attn);

    dim3 blk(256);
    // 1x1 kqv (384 ch) -> g_kqv ; q channels [128,256) scaled by DKH^-0.5
    conv_mma_kernel<1, 1, 0><<<dim3(8, 6, 8), blk>>>(
        x, w_kqv, b_kqv, kqv_ptr, 256, 384 * HW, 0, 128, 256, 0.25f);
    // fused rel-pos attention -> g_attn
    attn_kernel<<<dim3(8, 8, 8), 128>>>(krw, krh);
    // 1x1 attn projection -> out channels [384,512)
    conv_mma_kernel<1, 1, 0><<<dim3(8, 2, 8), blk>>>(
        attn_ptr, w_attn, b_attn, out, 128, 512 * HW, 384, 0, 0, 1.f);
    // conv3x3 -> out channels [0,384)
    conv_mma_kernel<3, 3, 1><<<dim3(8, 6, 8), blk>>>(
        x, w_out, b_out, out, 256, 512 * HW, 0, 0, 0, 1.f);
}

// round 7
// speedup vs baseline: 1.3587x; 1.1026x over previous
#include <cuda_runtime.h>
#include <cstdint>

#define NB   8
#define HH   32
#define WW   32
#define HW   1024
#define NHD  8
#define DKH_ 16

// scratch (no cudaMalloc allowed)
__device__ float g_kqv[(size_t)NB * 384 * HW];   // (N,384,HW): k[0:128], q[128:256] (scaled), v[256:384]
__device__ float g_attn[(size_t)NB * 128 * HW];  // flat (N,NH,HW,DVH) == raw-reshape (N,128,HW)

// ---------------------------------------------------------------------------
__device__ __forceinline__ float tf32hi(float x) {
    uint32_t u;
    asm("cvt.rna.tf32.f32 %0, %1;" : "=r"(u) : "f"(x));
    return __uint_as_float(u);
}

__device__ __forceinline__ void mma8(float4& d, const float* a, const float* b) {
    asm volatile(
        "mma.sync.aligned.m16n8k8.row.col.f32.tf32.tf32.f32 "
        "{%0,%1,%2,%3},{%4,%5,%6,%7},{%8,%9},{%0,%1,%2,%3};"
        : "+f"(d.x), "+f"(d.y), "+f"(d.z), "+f"(d.w)
        : "r"(__float_as_uint(a[0])), "r"(__float_as_uint(a[1])),
          "r"(__float_as_uint(a[2])), "r"(__float_as_uint(a[3])),
          "r"(__float_as_uint(b[0])), "r"(__float_as_uint(b[1])));
}

// Per-stage SMEM: fragment-permuted A (one float4 per thread per (mt,ks)),
// paired B (float2 = {B[k][n], B[k+4][n]}), row pad 132 -> conflict-free.
struct Stage {
    float4 Ah[2][2][2][32];   // [wm][mt][ks][lane]
    float4 Al[2][2][2][32];
    float2 Bh[2][4][132];     // [ks][tig][n]
    float2 Bl[2][4][132];
};
#define SMEMB ((int)(2 * sizeof(Stage)))

// ---------------------------------------------------------------------------
// Implicit-im2col conv GEMM on tensor pipe (tf32 3-term split, fp32-grade).
// Tile 64(Cout) x 128(pix), BK=16, 8 warps 2x4, warp tile 32x32.
// Double-buffered, division-free incremental im2col indexing.
// ---------------------------------------------------------------------------
template <int KH, int KW, int PAD>
__device__ __forceinline__ void load_b8(const float* xb, int& ci0, int& rr0,
                                        int ph, int pw, int P, float* rB)
{
    if (KH == 1) {
        const float* p = xb + (size_t)ci0 * HW + P;   // ci0 tracks kg for 1x1
#pragma unroll
        for (int r = 0; r < 8; r++) { rB[r] = __ldg(p); p += HW; }
        ci0 += 16;
    } else {
        int ci = ci0, rr = rr0;
#pragma unroll
        for (int r = 0; r < 8; r++) {
            int kh  = (rr >= 6) ? 2 : ((rr >= 3) ? 1 : 0);
            int kw2 = rr - kh * 3;
            int hh = ph + kh - PAD, wp = pw + kw2 - PAD;
            bool v = ((unsigned)hh < HH) && ((unsigned)wp < WW);
            rB[r] = v ? __ldg(xb + (size_t)ci * HW + hh * WW + wp) : 0.f;
            if (++rr == 9) { rr = 0; ++ci; }
        }
        rr0 += 16;
        if (rr0 >= 9) { rr0 -= 9; ci0++; }
        if (rr0 >= 9) { rr0 -= 9; ci0++; }
    }
}

template <int KH, int KW, int PAD>
__global__ __launch_bounds__(256, 2) void conv_mma_kernel(
    const float* __restrict__ x, const float* __restrict__ w,
    const float* __restrict__ bias, float* __restrict__ out,
    int Cin, int oss, int cho, int qlo, int qhi, float qscale)
{
    extern __shared__ char smem_raw[];
    Stage* st = reinterpret_cast<Stage*>(smem_raw);

    const int Ktot = Cin * KH * KW;
    const int NC   = Ktot >> 4;
    const int tid = threadIdx.x, lane = tid & 31, warp = tid >> 5;
    const int wm = warp >> 2, wn = warp & 3, gid = lane >> 2, tig = lane & 3;
    const int p0 = blockIdx.x * 128, m0 = blockIdx.y * 64, n = blockIdx.z;

    // A staging ids: thread loads w[m0+am][ak4..ak4+3]
    const int am = tid >> 2, ak4 = (tid & 3) << 2;
    const int awm = am >> 5, amt = (am >> 4) & 1, agid = am & 7, aselm = (am >> 3) & 1;
    const int aks = ak4 >> 3, aselk = (ak4 >> 2) & 1, acomp = aselm + 2 * aselk;
    // B staging ids: thread handles pixel bp, k-range kk0..kk0+7 (consecutive)
    const int bp = tid & 127, bks = tid >> 7, kk0 = bks << 3;
    const int P = p0 + bp, ph = P >> 5, pw = P & 31;

    const float* xb = x + (size_t)n * Cin * HW;
    const float* wb = w + (size_t)(m0 + am) * Ktot + ak4;

    int ci0 = (KH == 1) ? kk0 : 0;
    int rr0 = kk0;   // kk0 < 9 always

    float4 acc[2][4];
#pragma unroll
    for (int i = 0; i < 2; i++)
#pragma unroll
        for (int j = 0; j < 4; j++) acc[i][j] = make_float4(0.f, 0.f, 0.f, 0.f);

    float4 rA;
    float  rB[8];

    // ---- prologue: chunk 0 ----
    rA = *(const float4*)wb; wb += 16;
    load_b8<KH, KW, PAD>(xb, ci0, rr0, ph, pw, P, rB);
    {
        Stage& D = st[0];
        float4 hv, lv;
        hv.x = tf32hi(rA.x); lv.x = rA.x - hv.x;
        hv.y = tf32hi(rA.y); lv.y = rA.y - hv.y;
        hv.z = tf32hi(rA.z); lv.z = rA.z - hv.z;
        hv.w = tf32hi(rA.w); lv.w = rA.w - hv.w;
        float* ah = (float*)&D.Ah[awm][amt][aks][0] + agid * 16 + acomp;
        ah[0] = hv.x; ah[4] = hv.y; ah[8] = hv.z; ah[12] = hv.w;
        float* al = (float*)&D.Al[awm][amt][aks][0] + agid * 16 + acomp;
        al[0] = lv.x; al[4] = lv.y; al[8] = lv.z; al[12] = lv.w;
#pragma unroll
        for (int r = 0; r < 8; r++) {
            float v = rB[r], h = tf32hi(v);
            int tg = r & 3, comp = (r >> 2) & 1;
            ((float*)&D.Bh[bks][tg][bp])[comp] = h;
            ((float*)&D.Bl[bks][tg][bp])[comp] = v - h;
        }
    }
    __syncthreads();

    for (int c = 0; c < NC; c++) {
        const bool more = (c + 1 < NC);
        if (more) {   // issue next chunk's globals early
            rA = *(const float4*)wb; wb += 16;
            load_b8<KH, KW, PAD>(xb, ci0, rr0, ph, pw, P, rB);
        }

        const Stage& S = st[c & 1];
#pragma unroll
        for (int ks = 0; ks < 2; ks++) {
            float4 ah0 = S.Ah[wm][0][ks][lane], ah1 = S.Ah[wm][1][ks][lane];
            float4 al0 = S.Al[wm][0][ks][lane], al1 = S.Al[wm][1][ks][lane];
            float2 bh[4], bl[4];
#pragma unroll
            for (int nt = 0; nt < 4; nt++) {
                int nn = wn * 32 + nt * 8 + gid;
                bh[nt] = S.Bh[ks][tig][nn];
                bl[nt] = S.Bl[ks][tig][nn];
            }
#pragma unroll
            for (int nt = 0; nt < 4; nt++) {
                mma8(acc[0][nt], (const float*)&ah0, (const float*)&bh[nt]);
                mma8(acc[1][nt], (const float*)&ah1, (const float*)&bh[nt]);
                mma8(acc[0][nt], (const float*)&al0, (const float*)&bh[nt]);
                mma8(acc[1][nt], (const float*)&al1, (const float*)&bh[nt]);
                mma8(acc[0][nt], (const float*)&ah0, (const float*)&bl[nt]);
                mma8(acc[1][nt], (const float*)&ah1, (const float*)&bl[nt]);
            }
        }

        if (more) {
            Stage& D = st[(c + 1) & 1];
            float4 hv, lv;
            hv.x = tf32hi(rA.x); lv.x = rA.x - hv.x;
            hv.y = tf32hi(rA.y); lv.y = rA.y - hv.y;
            hv.z = tf32hi(rA.z); lv.z = rA.z - hv.z;
            hv.w = tf32hi(rA.w); lv.w = rA.w - hv.w;
            float* ah = (float*)&D.Ah[awm][amt][aks][0] + agid * 16 + acomp;
            ah[0] = hv.x; ah[4] = hv.y; ah[8] = hv.z; ah[12] = hv.w;
            float* al = (float*)&D.Al[awm][amt][aks][0] + agid * 16 + acomp;
            al[0] = lv.x; al[4] = lv.y; al[8] = lv.z; al[12] = lv.w;
#pragma unroll
            for (int r = 0; r < 8; r++) {
                float v = rB[r], h = tf32hi(v);
                int tg = r & 3, comp = (r >> 2) & 1;
                ((float*)&D.Bh[bks][tg][bp])[comp] = h;
                ((float*)&D.Bl[bks][tg][bp])[comp] = v - h;
            }
        }
        __syncthreads();
    }

#pragma unroll
    for (int mt = 0; mt < 2; mt++) {
        int r0 = m0 + wm * 32 + mt * 16 + gid;
        int r1 = r0 + 8;
        float b0 = bias[r0], b1 = bias[r1];
        float s0 = (r0 >= qlo && r0 < qhi) ? qscale : 1.f;
        float s1 = (r1 >= qlo && r1 < qhi) ? qscale : 1.f;
#pragma unroll
        for (int nt = 0; nt < 4; nt++) {
            int c0 = p0 + wn * 32 + nt * 8 + tig * 2;
            float2 v0, v1;
            v0.x = (acc[mt][nt].x + b0) * s0;
            v0.y = (acc[mt][nt].y + b0) * s0;
            v1.x = (acc[mt][nt].z + b1) * s1;
            v1.y = (acc[mt][nt].w + b1) * s1;
            *(float2*)(out + (size_t)n * oss + (size_t)(cho + r0) * HW + c0) = v0;
            *(float2*)(out + (size_t)n * oss + (size_t)(cho + r1) * HW + c0) = v1;
        }
    }
}

// ---------------------------------------------------------------------------
// Fused relative-position attention, flash style (unchanged from R6).
// ---------------------------------------------------------------------------
__global__ __launch_bounds__(128) void attn_kernel(
    const float* __restrict__ krw, const float* __restrict__ krh)
{
    __shared__ float srw[32][128];
    __shared__ float srh[32][128];
    __shared__ float Ks[16][64];
    __shared__ float Vs[16][64];

    const int tid = threadIdx.x;
    const int b = blockIdx.z, h = blockIdx.y;
    const int m = blockIdx.x * 128 + tid;

    const float* kb = g_kqv + ((size_t)b * 384 + h * DKH_) * HW;
    const float* qb = g_kqv + ((size_t)b * 384 + 128 + h * DKH_) * HW;
    const float* vb = g_kqv + ((size_t)b * 384 + 256 + h * DKH_) * HW;

    float q[16];
#pragma unroll
    for (int d = 0; d < 16; d++) q[d] = qb[(size_t)d * HW + m];

    const int xr = m >> 5, yc = m & 31;
#pragma unroll 1
    for (int j = 0; j < 32; j++) {
        const float* kw_ = krw + (j + 31 - yc) * DKH_;
        const float* kh_ = krh + (j + 31 - xr) * DKH_;
        float s1 = 0.f, s2 = 0.f;
#pragma unroll
        for (int d = 0; d < 16; d++) {
            s1 = fmaf(q[d], kw_[d], s1);
            s2 = fmaf(q[d], kh_[d], s2);
        }
        srw[j][tid] = s1;
        srh[j][tid] = s2;
    }

    float mrun = -1e30f, l = 0.f;
    float acc[16];
#pragma unroll
    for (int d = 0; d < 16; d++) acc[d] = 0.f;

    for (int n0 = 0; n0 < HW; n0 += 64) {
        __syncthreads();
#pragma unroll
        for (int r = 0; r < 8; r++) {
            int e = tid + r * 128;
            int d = e >> 6, nn = e & 63;
            Ks[d][nn] = kb[(size_t)d * HW + n0 + nn];
            Vs[d][nn] = vb[(size_t)d * HW + n0 + nn];
        }
        __syncthreads();

#pragma unroll 1
        for (int ii = 0; ii < 2; ii++) {
            const int i = (n0 >> 5) + ii;
            const float rh = srh[i][tid];
            float sbuf[32];
#pragma unroll
            for (int j = 0; j < 32; j++) sbuf[j] = srw[j][tid] + rh;

#pragma unroll
            for (int d = 0; d < 16; d++) {
                const float qd = q[d];
#pragma unroll
                for (int jb = 0; jb < 8; jb++) {
                    float4 k4 = *(const float4*)&Ks[d][ii * 32 + jb * 4];
                    sbuf[jb * 4 + 0] = fmaf(qd, k4.x, sbuf[jb * 4 + 0]);
                    sbuf[jb * 4 + 1] = fmaf(qd, k4.y, sbuf[jb * 4 + 1]);
                    sbuf[jb * 4 + 2] = fmaf(qd, k4.z, sbuf[jb * 4 + 2]);
                    sbuf[jb * 4 + 3] = fmaf(qd, k4.w, sbuf[jb * 4 + 3]);
                }
            }

            float cmax = -1e30f;
#pragma unroll
            for (int j = 0; j < 32; j++) cmax = fmaxf(cmax, sbuf[j]);
            float newm = fmaxf(mrun, cmax);
            float corr = exp2f((mrun - newm) * 1.44269504f);
            l *= corr;
#pragma unroll
            for (int d = 0; d < 16; d++) acc[d] *= corr;

#pragma unroll
            for (int j = 0; j < 32; j++) {
                float p = exp2f((sbuf[j] - newm) * 1.44269504f);
                l += p;
                sbuf[j] = p;
            }

#pragma unroll
            for (int d = 0; d < 16; d++) {
                float a = acc[d];
#pragma unroll
                for (int jb = 0; jb < 8; jb++) {
                    float4 v4 = *(const float4*)&Vs[d][ii * 32 + jb * 4];
                    a = fmaf(sbuf[jb * 4 + 0], v4.x, a);
                    a = fmaf(sbuf[jb * 4 + 1], v4.y, a);
                    a = fmaf(sbuf[jb * 4 + 2], v4.z, a);
                    a = fmaf(sbuf[jb * 4 + 3], v4.w, a);
                }
                acc[d] = a;
            }
            mrun = newm;
        }
    }

    const float inv = 1.f / l;
    float* o = g_attn + (((size_t)b * NHD + h) * HW + m) * 16;
#pragma unroll
    for (int t = 0; t < 4; t++) {
        float4 v;
        v.x = acc[t * 4 + 0] * inv;
        v.y = acc[t * 4 + 1] * inv;
        v.z = acc[t * 4 + 2] * inv;
        v.w = acc[t * 4 + 3] * inv;
        *(float4*)(o + t * 4) = v;
    }
}

// ---------------------------------------------------------------------------
extern "C" void kernel_launch(void* const* d_in, const int* in_sizes, int n_in,
                              void* d_out, int out_size)
{
    const float* x      = (const float*)d_in[0];
    const float* w_out  = (const float*)d_in[1];
    const float* b_out  = (const float*)d_in[2];
    const float* w_kqv  = (const float*)d_in[3];
    const float* b_kqv  = (const float*)d_in[4];
    const float* w_attn = (const float*)d_in[5];
    const float* b_attn = (const float*)d_in[6];
    const float* krw    = (const float*)d_in[7];
    const float* krh    = (const float*)d_in[8];
    float* out = (float*)d_out;

    float *kqv_ptr = nullptr, *attn_ptr = nullptr;
    cudaGetSymbolAddress((void**)&kqv_ptr, g_kqv);
    cudaGetSymbolAddress((void**)&attn_ptr, g_attn);

    static cudaStream_t s2 = nullptr;
    static cudaEvent_t ev_fork = nullptr, ev_join = nullptr;
    if (s2 == nullptr) {
        cudaStreamCreateWithFlags(&s2, cudaStreamNonBlocking);
        cudaEventCreateWithFlags(&ev_fork, cudaEventDisableTiming);
        cudaEventCreateWithFlags(&ev_join, cudaEventDisableTiming);
        cudaFuncSetAttribute(conv_mma_kernel<3, 3, 1>,
                             cudaFuncAttributeMaxDynamicSharedMemorySize, SMEMB);
        cudaFuncSetAttribute(conv_mma_kernel<1, 1, 0>,
                             cudaFuncAttributeMaxDynamicSharedMemorySize, SMEMB);
    }

    // fork: conv3x3 (independent) runs on side stream, parallel to attn chain
    cudaEventRecord(ev_fork, 0);
    cudaStreamWaitEvent(s2, ev_fork, 0);
    conv_mma_kernel<3, 3, 1><<<dim3(8, 6, 8), 256, SMEMB, s2>>>(
        x, w_out, b_out, out, 256, 512 * HW, 0, 0, 0, 1.f);
    cudaEventRecord(ev_join, s2);

    // main chain: kqv -> attention -> projection
    conv_mma_kernel<1, 1, 0><<<dim3(8, 6, 8), 256, SMEMB>>>(
        x, w_kqv, b_kqv, kqv_ptr, 256, 384 * HW, 0, 128, 256, 0.25f);
    attn_kernel<<<dim3(8, 8, 8), 128>>>(krw, krh);
    conv_mma_kernel<1, 1, 0><<<dim3(8, 2, 8), 256, SMEMB>>>(
        attn_ptr, w_attn, b_attn, out, 128, 512 * HW, 384, 0, 0, 1.f);

    // join
    cudaStreamWaitEvent(0, ev_join, 0);
}

// round 11
// speedup vs baseline: 1.6083x; 1.1837x over previous
#include <cuda_runtime.h>
#include <cstdint>

#define NB   8
#define HH   32
#define WW   32
#define HW   1024
#define NHD  8
#define DKH_ 16

// scratch (no cudaMalloc allowed)
__device__ float g_kqv[(size_t)NB * 384 * HW];   // (N,384,HW): k[0:128], q[128:256] (scaled), v[256:384]
__device__ float g_attn[(size_t)NB * 128 * HW];  // flat (N,NH,HW,DVH) == raw-reshape (N,128,HW)

// ---------------------------------------------------------------------------
// bf16x3 split helpers
// ---------------------------------------------------------------------------
__device__ __forceinline__ uint32_t bfhi(float v) {   // bf16(v) bits in high16, RN-even
    uint32_t u = __float_as_uint(v);
    return (u + 0x7FFFu + ((u >> 16) & 1u)) & 0xFFFF0000u;
}
__device__ __forceinline__ uint32_t packlo(float l0, float l1) {  // low16 = bf16(l0)
    uint32_t r;
    asm("cvt.rn.bf16x2.f32 %0, %1, %2;" : "=r"(r) : "f"(l1), "f"(l0));
    return r;
}
__device__ __forceinline__ uint32_t f2u(float x) { return __float_as_uint(x); }
__device__ __forceinline__ float    u2f(uint32_t x) { return __uint_as_float(x); }

__device__ __forceinline__ void mmabf(float4& d,
                                      uint32_t a0, uint32_t a1, uint32_t a2, uint32_t a3,
                                      uint32_t b0, uint32_t b1) {
    asm volatile(
        "mma.sync.aligned.m16n8k16.row.col.f32.bf16.bf16.f32 "
        "{%0,%1,%2,%3},{%4,%5,%6,%7},{%8,%9},{%0,%1,%2,%3};"
        : "+f"(d.x), "+f"(d.y), "+f"(d.z), "+f"(d.w)
        : "r"(a0), "r"(a1), "r"(a2), "r"(a3), "r"(b0), "r"(b1));
}

// Stage: A fragments pre-permuted (one float4 = one lane's a-frag), B pre-paired
// uint2 rows padded to 132 (bank-conflict-free for both STS and frag LDS).
struct Stage {
    float4 A1[128];       // [(wm*2+mt)*32 + lane]  (hi split)
    float4 A2[128];       // (lo split)
    uint2  B1[4][132];    // [tig][n]: .x={b[2t][n],b[2t+1][n]}, .y={b[2t+8],b[2t+9]}
    uint2  B2[4][132];
};

// ---------------------------------------------------------------------------
// Implicit-im2col conv GEMM, bf16x3 on tensor pipe (fp32-grade, ~1e-5).
// Tile 64(Cout) x 128(pix), BK=16, 8 warps 2x4, warp tile 32x32,
// double-buffered static SMEM (2 x 12.25KB).
// ---------------------------------------------------------------------------
template <int KH, int PAD>
__global__ __launch_bounds__(256, 2) void conv_bf16_kernel(
    const float* __restrict__ x, const float* __restrict__ w,
    const float* __restrict__ bias, float* __restrict__ out,
    int Cin, int oss, int cho, int qlo, int qhi, float qscale)
{
    __shared__ Stage st[2];
    const int Ktot = Cin * KH * KH;
    const int NC   = Ktot >> 4;
    const int tid = threadIdx.x, lane = tid & 31, warp = tid >> 5;
    const int wm = warp >> 2, wn = warp & 3, gid = lane >> 2, tig = lane & 3;
    const int p0 = blockIdx.x * 128, m0 = blockIdx.y * 64, n = blockIdx.z;

    // A staging: slot = one lane-frag float4; threads <128 build hi, >=128 lo.
    const int  slot   = tid & 127;
    const bool hiPart = tid < 128;
    const int  awm = slot >> 6, amt = (slot >> 5) & 1, aln = slot & 31;
    const int  agid = aln >> 2, atig = aln & 3;
    const int  arow0 = m0 + awm * 32 + amt * 16 + agid;
    const float* wp0 = w + (size_t)arow0 * Ktot + 2 * atig;
    const float* wp1 = wp0 + (size_t)8 * Ktot;

    // B staging: thread owns pixel bn, tig rows {btg, btg+2}.
    const int bn = tid & 127, btg = tid >> 7;
    const int P = p0 + bn, ph = P >> 5, pw = P & 31;
    const float* xb = x + (size_t)n * Cin * HW;

    float4 acc[2][4];
#pragma unroll
    for (int i = 0; i < 2; i++)
#pragma unroll
        for (int j = 0; j < 4; j++) acc[i][j] = make_float4(0.f, 0.f, 0.f, 0.f);

    float2 w00, w10, w01, w11;
    float  rB[2][4];

    auto ldB = [&](int kg) -> float {
        if (KH == 1) return __ldg(xb + (size_t)kg * HW + P);
        unsigned ci = (unsigned)kg / 9u, rr = (unsigned)kg - 9u * ci;
        unsigned kh = rr / 3u, kw2 = rr - 3u * kh;
        int hh = ph + (int)kh - PAD, wq = pw + (int)kw2 - PAD;
        return ((unsigned)hh < HH && (unsigned)wq < WW)
                   ? __ldg(xb + (size_t)ci * HW + hh * WW + wq) : 0.f;
    };
    auto loadA = [&](int k0) {
        w00 = *(const float2*)(wp0 + k0);
        w10 = *(const float2*)(wp1 + k0);
        w01 = *(const float2*)(wp0 + k0 + 8);
        w11 = *(const float2*)(wp1 + k0 + 8);
    };
    auto loadB = [&](int k0) {
#pragma unroll
        for (int s = 0; s < 2; s++) {
            int kb = k0 + 2 * (btg + 2 * s);
            rB[s][0] = ldB(kb);     rB[s][1] = ldB(kb + 1);
            rB[s][2] = ldB(kb + 8); rB[s][3] = ldB(kb + 9);
        }
    };
    auto storeStage = [&](Stage& D) {
        if (hiPart) {
            D.A1[slot] = make_float4(
                u2f(__byte_perm(bfhi(w00.x), bfhi(w00.y), 0x7632)),
                u2f(__byte_perm(bfhi(w10.x), bfhi(w10.y), 0x7632)),
                u2f(__byte_perm(bfhi(w01.x), bfhi(w01.y), 0x7632)),
                u2f(__byte_perm(bfhi(w11.x), bfhi(w11.y), 0x7632)));
        } else {
            uint32_t h;
            float l00, l01, l10, l11, l20, l21, l30, l31;
            h = bfhi(w00.x); l00 = w00.x - u2f(h);
            h = bfhi(w00.y); l01 = w00.y - u2f(h);
            h = bfhi(w10.x); l10 = w10.x - u2f(h);
            h = bfhi(w10.y); l11 = w10.y - u2f(h);
            h = bfhi(w01.x); l20 = w01.x - u2f(h);
            h = bfhi(w01.y); l21 = w01.y - u2f(h);
            h = bfhi(w11.x); l30 = w11.x - u2f(h);
            h = bfhi(w11.y); l31 = w11.y - u2f(h);
            D.A2[slot] = make_float4(
                u2f(packlo(l00, l01)), u2f(packlo(l10, l11)),
                u2f(packlo(l20, l21)), u2f(packlo(l30, l31)));
        }
#pragma unroll
        for (int s = 0; s < 2; s++) {
            int tg = btg + 2 * s;
            uint32_t h0 = bfhi(rB[s][0]), h1 = bfhi(rB[s][1]);
            uint32_t h2 = bfhi(rB[s][2]), h3 = bfhi(rB[s][3]);
            D.B1[tg][bn] = make_uint2(__byte_perm(h0, h1, 0x7632),
                                      __byte_perm(h2, h3, 0x7632));
            D.B2[tg][bn] = make_uint2(
                packlo(rB[s][0] - u2f(h0), rB[s][1] - u2f(h1)),
                packlo(rB[s][2] - u2f(h2), rB[s][3] - u2f(h3)));
        }
    };

    // prologue
    loadA(0); loadB(0);
    storeStage(st[0]);
    __syncthreads();

    for (int c = 0; c < NC; c++) {
        const bool more = (c + 1 < NC);
        if (more) { loadA((c + 1) * 16); loadB((c + 1) * 16); }

        const Stage& S = st[c & 1];
        float4 A1f[2], A2f[2];
        A1f[0] = S.A1[(wm * 2 + 0) * 32 + lane];
        A1f[1] = S.A1[(wm * 2 + 1) * 32 + lane];
        A2f[0] = S.A2[(wm * 2 + 0) * 32 + lane];
        A2f[1] = S.A2[(wm * 2 + 1) * 32 + lane];
        uint2 B1f[4], B2f[4];
#pragma unroll
        for (int nt = 0; nt < 4; nt++) {
            int nn = wn * 32 + nt * 8 + gid;
            B1f[nt] = S.B1[tig][nn];
            B2f[nt] = S.B2[tig][nn];
        }
#pragma unroll
        for (int mt = 0; mt < 2; mt++) {
            uint32_t a10 = f2u(A1f[mt].x), a11 = f2u(A1f[mt].y),
                     a12 = f2u(A1f[mt].z), a13 = f2u(A1f[mt].w);
            uint32_t a20 = f2u(A2f[mt].x), a21 = f2u(A2f[mt].y),
                     a22 = f2u(A2f[mt].z), a23 = f2u(A2f[mt].w);
#pragma unroll
            for (int nt = 0; nt < 4; nt++) {
                mmabf(acc[mt][nt], a10, a11, a12, a13, B1f[nt].x, B1f[nt].y);
                mmabf(acc[mt][nt], a10, a11, a12, a13, B2f[nt].x, B2f[nt].y);
                mmabf(acc[mt][nt], a20, a21, a22, a23, B1f[nt].x, B1f[nt].y);
            }
        }
        if (more) storeStage(st[(c + 1) & 1]);
        __syncthreads();
    }

#pragma unroll
    for (int mt = 0; mt < 2; mt++) {
        int r0 = m0 + wm * 32 + mt * 16 + gid;
        int r1 = r0 + 8;
        float b0 = bias[r0], b1 = bias[r1];
        float s0 = (r0 >= qlo && r0 < qhi) ? qscale : 1.f;
        float s1 = (r1 >= qlo && r1 < qhi) ? qscale : 1.f;
#pragma unroll
        for (int nt = 0; nt < 4; nt++) {
            int c0 = p0 + wn * 32 + nt * 8 + tig * 2;
            float2 v0, v1;
            v0.x = (acc[mt][nt].x + b0) * s0;
            v0.y = (acc[mt][nt].y + b0) * s0;
            v1.x = (acc[mt][nt].z + b1) * s1;
            v1.y = (acc[mt][nt].w + b1) * s1;
            *(float2*)(out + (size_t)n * oss + (size_t)(cho + r0) * HW + c0) = v0;
            *(float2*)(out + (size_t)n * oss + (size_t)(cho + r1) * HW + c0) = v1;
        }
    }
}

// ---------------------------------------------------------------------------
// Fused relative-position attention, flash style (unchanged).
// ---------------------------------------------------------------------------
__global__ __launch_bounds__(128) void attn_kernel(
    const float* __restrict__ krw, const float* __restrict__ krh)
{
    __shared__ float srw[32][128];
    __shared__ float srh[32][128];
    __shared__ float Ks[16][64];
    __shared__ float Vs[16][64];

    const int tid = threadIdx.x;
    const int b = blockIdx.z, h = blockIdx.y;
    const int m = blockIdx.x * 128 + tid;

    const float* kb = g_kqv + ((size_t)b * 384 + h * DKH_) * HW;
    const float* qb = g_kqv + ((size_t)b * 384 + 128 + h * DKH_) * HW;
    const float* vb = g_kqv + ((size_t)b * 384 + 256 + h * DKH_) * HW;

    float q[16];
#pragma unroll
    for (int d = 0; d < 16; d++) q[d] = qb[(size_t)d * HW + m];

    const int xr = m >> 5, yc = m & 31;
#pragma unroll 1
    for (int j = 0; j < 32; j++) {
        const float* kw_ = krw + (j + 31 - yc) * DKH_;
        const float* kh_ = krh + (j + 31 - xr) * DKH_;
        float s1 = 0.f, s2 = 0.f;
#pragma unroll
        for (int d = 0; d < 16; d++) {
            s1 = fmaf(q[d], kw_[d], s1);
            s2 = fmaf(q[d], kh_[d], s2);
        }
        srw[j][tid] = s1;
        srh[j][tid] = s2;
    }

    float mrun = -1e30f, l = 0.f;
    float acc[16];
#pragma unroll
    for (int d = 0; d < 16; d++) acc[d] = 0.f;

    for (int n0 = 0; n0 < HW; n0 += 64) {
        __syncthreads();
#pragma unroll
        for (int r = 0; r < 8; r++) {
            int e = tid + r * 128;
            int d = e >> 6, nn = e & 63;
            Ks[d][nn] = kb[(size_t)d * HW + n0 + nn];
            Vs[d][nn] = vb[(size_t)d * HW + n0 + nn];
        }
        __syncthreads();

#pragma unroll 1
        for (int ii = 0; ii < 2; ii++) {
            const int i = (n0 >> 5) + ii;
            const float rh = srh[i][tid];
            float sbuf[32];
#pragma unroll
            for (int j = 0; j < 32; j++) sbuf[j] = srw[j][tid] + rh;

#pragma unroll
            for (int d = 0; d < 16; d++) {
                const float qd = q[d];
#pragma unroll
                for (int jb = 0; jb < 8; jb++) {
                    float4 k4 = *(const float4*)&Ks[d][ii * 32 + jb * 4];
                    sbuf[jb * 4 + 0] = fmaf(qd, k4.x, sbuf[jb * 4 + 0]);
                    sbuf[jb * 4 + 1] = fmaf(qd, k4.y, sbuf[jb * 4 + 1]);
                    sbuf[jb * 4 + 2] = fmaf(qd, k4.z, sbuf[jb * 4 + 2]);
                    sbuf[jb * 4 + 3] = fmaf(qd, k4.w, sbuf[jb * 4 + 3]);
                }
            }

            float cmax = -1e30f;
#pragma unroll
            for (int j = 0; j < 32; j++) cmax = fmaxf(cmax, sbuf[j]);
            float newm = fmaxf(mrun, cmax);
            float corr = exp2f((mrun - newm) * 1.44269504f);
            l *= corr;
#pragma unroll
            for (int d = 0; d < 16; d++) acc[d] *= corr;

#pragma unroll
            for (int j = 0; j < 32; j++) {
                float p = exp2f((sbuf[j] - newm) * 1.44269504f);
                l += p;
                sbuf[j] = p;
            }

#pragma unroll
            for (int d = 0; d < 16; d++) {
                float a = acc[d];
#pragma unroll
                for (int jb = 0; jb < 8; jb++) {
                    float4 v4 = *(const float4*)&Vs[d][ii * 32 + jb * 4];
                    a = fmaf(sbuf[jb * 4 + 0], v4.x, a);
                    a = fmaf(sbuf[jb * 4 + 1], v4.y, a);
                    a = fmaf(sbuf[jb * 4 + 2], v4.z, a);
                    a = fmaf(sbuf[jb * 4 + 3], v4.w, a);
                }
                acc[d] = a;
            }
            mrun = newm;
        }
    }

    const float inv = 1.f / l;
    float* o = g_attn + (((size_t)b * NHD + h) * HW + m) * 16;
#pragma unroll
    for (int t = 0; t < 4; t++) {
        float4 v;
        v.x = acc[t * 4 + 0] * inv;
        v.y = acc[t * 4 + 1] * inv;
        v.z = acc[t * 4 + 2] * inv;
        v.w = acc[t * 4 + 3] * inv;
        *(float4*)(o + t * 4) = v;
    }
}

// ---------------------------------------------------------------------------
extern "C" void kernel_launch(void* const* d_in, const int* in_sizes, int n_in,
                              void* d_out, int out_size)
{
    const float* x      = (const float*)d_in[0];
    const float* w_out  = (const float*)d_in[1];
    const float* b_out  = (const float*)d_in[2];
    const float* w_kqv  = (const float*)d_in[3];
    const float* b_kqv  = (const float*)d_in[4];
    const float* w_attn = (const float*)d_in[5];
    const float* b_attn = (const float*)d_in[6];
    const float* krw    = (const float*)d_in[7];
    const float* krh    = (const float*)d_in[8];
    float* out = (float*)d_out;

    float *kqv_ptr = nullptr, *attn_ptr = nullptr;
    cudaGetSymbolAddress((void**)&kqv_ptr, g_kqv);
    cudaGetSymbolAddress((void**)&attn_ptr, g_attn);

    static cudaStream_t s2 = nullptr;
    static cudaEvent_t ev_fork = nullptr, ev_join = nullptr;
    if (s2 == nullptr) {
        cudaStreamCreateWithFlags(&s2, cudaStreamNonBlocking);
        cudaEventCreateWithFlags(&ev_fork, cudaEventDisableTiming);
        cudaEventCreateWithFlags(&ev_join, cudaEventDisableTiming);
    }

    // fork: conv3x3 (independent of attn chain) on side stream
    cudaEventRecord(ev_fork, 0);
    cudaStreamWaitEvent(s2, ev_fork, 0);
    conv_bf16_kernel<3, 1><<<dim3(8, 6, 8), 256, 0, s2>>>(
        x, w_out, b_out, out, 256, 512 * HW, 0, 0, 0, 1.f);
    cudaEventRecord(ev_join, s2);

    // main chain: kqv -> attention -> projection
    conv_bf16_kernel<1, 0><<<dim3(8, 6, 8), 256>>>(
        x, w_kqv, b_kqv, kqv_ptr, 256, 384 * HW, 0, 128, 256, 0.25f);
    attn_kernel<<<dim3(8, 8, 8), 128>>>(krw, krh);
    conv_bf16_kernel<1, 0><<<dim3(8, 2, 8), 256>>>(
        attn_ptr, w_attn, b_attn, out, 128, 512 * HW, 384, 0, 0, 1.f);

    // join
    cudaStreamWaitEvent(0, ev_join, 0);
}

// round 15
// speedup vs baseline: 2.0942x; 1.3022x over previous
#include <cuda_runtime.h>
#include <cstdint>

#define NB   8
#define HH   32
#define WW   32
#define HW   1024
#define NHD  8
#define DKH_ 16
#define HWP  1088   // 34*32 padded rows

// ---------------- scratch (no cudaMalloc allowed) ----------------
__device__ float g_kqv[(size_t)NB * 384 * HW];
__device__ float g_attn[(size_t)NB * 128 * HW];
__device__ float g_xs[(size_t)NB * 3 * 256 * HWP];          // [img][kw][ci][34][32]
__device__ uint2 g_B3h[(size_t)NB * 144 * 4 * HW];          // [img][c16][tig][pix]
__device__ uint2 g_B3l[(size_t)NB * 144 * 4 * HW];
__device__ uint2 g_Bkh[(size_t)NB * 16 * 4 * HW];
__device__ uint2 g_Bkl[(size_t)NB * 16 * 4 * HW];
__device__ uint2 g_Bph[(size_t)NB * 8 * 4 * HW];
__device__ uint2 g_Bpl[(size_t)NB * 8 * 4 * HW];
__device__ float4 g_A3h[6 * 144 * 128], g_A3l[6 * 144 * 128];
__device__ float4 g_Akh[6 * 16 * 128],  g_Akl[6 * 16 * 128];
__device__ float4 g_Aph[2 * 8 * 128],   g_Apl[2 * 8 * 128];

// ---------------- bf16x3 split helpers (identical to R11) ----------------
__device__ __forceinline__ uint32_t bfhi(float v) {
    uint32_t u = __float_as_uint(v);
    return (u + 0x7FFFu + ((u >> 16) & 1u)) & 0xFFFF0000u;
}
__device__ __forceinline__ uint32_t packlo(float l0, float l1) {
    uint32_t r;
    asm("cvt.rn.bf16x2.f32 %0, %1, %2;" : "=r"(r) : "f"(l1), "f"(l0));
    return r;
}
__device__ __forceinline__ uint32_t f2u(float x) { return __float_as_uint(x); }
__device__ __forceinline__ float    u2f(uint32_t x) { return __uint_as_float(x); }

__device__ __forceinline__ void pack4(float a, float b, float c, float d,
                                      uint2& hi, uint2& lo) {
    uint32_t ha = bfhi(a), hb = bfhi(b), hc = bfhi(c), hd = bfhi(d);
    hi.x = __byte_perm(ha, hb, 0x7632);
    hi.y = __byte_perm(hc, hd, 0x7632);
    lo.x = packlo(a - u2f(ha), b - u2f(hb));
    lo.y = packlo(c - u2f(hc), d - u2f(hd));
}

__device__ __forceinline__ void mmabf(float4& d,
                                      uint32_t a0, uint32_t a1, uint32_t a2, uint32_t a3,
                                      uint32_t b0, uint32_t b1) {
    asm volatile(
        "mma.sync.aligned.m16n8k16.row.col.f32.bf16.bf16.f32 "
        "{%0,%1,%2,%3},{%4,%5,%6,%7},{%8,%9},{%0,%1,%2,%3};"
        : "+f"(d.x), "+f"(d.y), "+f"(d.z), "+f"(d.w)
        : "r"(a0), "r"(a1), "r"(a2), "r"(a3), "r"(b0), "r"(b1));
}

// ---------------- prepass: shifted, padded x copies ----------------
__global__ __launch_bounds__(256) void xshift_kernel(const float* __restrict__ x)
{
    __shared__ float s[1024];
    const int ci = blockIdx.x, img = blockIdx.y, tid = threadIdx.x;
    const float* src = x + ((size_t)img * 256 + ci) * HW;
    ((float4*)s)[tid] = ((const float4*)src)[tid];
    __syncthreads();
    for (int idx = tid; idx < 3 * HWP; idx += 256) {
        int kw = idx / HWP, rem = idx - kw * HWP;
        int r = rem >> 5, w = rem & 31;
        int h = r - 1, wp = w + kw - 1;
        float v = ((unsigned)h < HH && (unsigned)wp < WW) ? s[h * 32 + wp] : 0.f;
        g_xs[((size_t)(img * 3 + kw) * 256 + ci) * HWP + rem] = v;
    }
}

// ---------------- prepass: weights -> fragment layout ----------------
__global__ __launch_bounds__(128) void aprep_kernel(
    const float* __restrict__ W, float4* __restrict__ Ah, float4* __restrict__ Al,
    int Ktot)
{
    const int c16 = blockIdx.x, mblk = blockIdx.y, slot = threadIdx.x;
    const int awm = slot >> 6, amt = (slot >> 5) & 1, aln = slot & 31;
    const int agid = aln >> 2, atig = aln & 3;
    const int r0 = mblk * 64 + awm * 32 + amt * 16 + agid;
    const int k0 = c16 * 16 + 2 * atig;
    const float* w0 = W + (size_t)r0 * Ktot + k0;
    const float* w1 = W + (size_t)(r0 + 8) * Ktot + k0;
    float2 a = *(const float2*)w0,       b = *(const float2*)w1;
    float2 c = *(const float2*)(w0 + 8), d = *(const float2*)(w1 + 8);
    uint2 h0, l0, h1, l1;
    pack4(a.x, a.y, b.x, b.y, h0, l0);
    pack4(c.x, c.y, d.x, d.y, h1, l1);
    const int o = (mblk * gridDim.x + c16) * 128 + slot;
    Ah[o] = make_float4(u2f(h0.x), u2f(h0.y), u2f(h1.x), u2f(h1.y));
    Al[o] = make_float4(u2f(l0.x), u2f(l0.y), u2f(l1.x), u2f(l1.y));
}

// ---------------- prepass: 1x1 operand (direct channel reads) ----------------
__global__ __launch_bounds__(256) void bprep1_kernel(
    const float* __restrict__ src, uint2* __restrict__ Bh, uint2* __restrict__ Bl,
    int Cin)
{
    const int tig = blockIdx.x, c16 = blockIdx.y, img = blockIdx.z;
    const int n0 = threadIdx.x * 4;
    const int kb = c16 * 16 + 2 * tig;
    const float* base = src + (size_t)img * Cin * HW + n0;
    float4 v0 = *(const float4*)(base + (size_t)(kb    ) * HW);
    float4 v1 = *(const float4*)(base + (size_t)(kb + 1) * HW);
    float4 v2 = *(const float4*)(base + (size_t)(kb + 8) * HW);
    float4 v3 = *(const float4*)(base + (size_t)(kb + 9) * HW);
    const float *p0 = (const float*)&v0, *p1 = (const float*)&v1;
    const float *p2 = (const float*)&v2, *p3 = (const float*)&v3;
    uint2 h[4], l[4];
#pragma unroll
    for (int e = 0; e < 4; e++) pack4(p0[e], p1[e], p2[e], p3[e], h[e], l[e]);
    size_t o = (((size_t)img * gridDim.y + c16) * 4 + tig) * HW + n0;
    *(uint4*)&Bh[o]     = *(uint4*)&h[0];
    *(uint4*)&Bh[o + 2] = *(uint4*)&h[2];
    *(uint4*)&Bl[o]     = *(uint4*)&l[0];
    *(uint4*)&Bl[o + 2] = *(uint4*)&l[2];
}

// ---------------- prepass: 3x3 im2col operand (from g_xs) ----------------
__global__ __launch_bounds__(256) void bprep3_kernel(
    uint2* __restrict__ Bh, uint2* __restrict__ Bl)
{
    const int tig = blockIdx.x, c16 = blockIdx.y, img = blockIdx.z;
    const int n0 = threadIdx.x * 4;
    const int ph = n0 >> 5, w0 = n0 & 31;
    const int kb = c16 * 16 + 2 * tig;
    const int ks[4] = {kb, kb + 1, kb + 8, kb + 9};
    float4 v[4];
#pragma unroll
    for (int j = 0; j < 4; j++) {
        int k = ks[j];
        unsigned ci = (unsigned)k / 9u, rr = (unsigned)k - 9u * ci;
        int kh = (rr >= 6) ? 2 : ((rr >= 3) ? 1 : 0);
        int kw = (int)rr - 3 * kh;
        v[j] = *(const float4*)(g_xs + ((size_t)(img * 3 + kw) * 256 + ci) * HWP
                                + (ph + kh) * 32 + w0);
    }
    const float *p0 = (const float*)&v[0], *p1 = (const float*)&v[1];
    const float *p2 = (const float*)&v[2], *p3 = (const float*)&v[3];
    uint2 h[4], l[4];
#pragma unroll
    for (int e = 0; e < 4; e++) pack4(p0[e], p1[e], p2[e], p3[e], h[e], l[e]);
    size_t o = (((size_t)img * 144 + c16) * 4 + tig) * HW + n0;
    *(uint4*)&Bh[o]     = *(uint4*)&h[0];
    *(uint4*)&Bh[o + 2] = *(uint4*)&h[2];
    *(uint4*)&Bl[o]     = *(uint4*)&l[0];
    *(uint4*)&Bl[o + 2] = *(uint4*)&l[2];
}

// ---------------- lean bf16x3 GEMM: BK=32, double-buffered ----------------
#define GEMM_SMEM (8 * 128 * 16 + 8 * 4 * 132 * 8)   // 50176 B

__global__ __launch_bounds__(256, 2) void gemm_bf16(
    const float4* __restrict__ Ah, const float4* __restrict__ Al,
    const uint2* __restrict__ Bh, const uint2* __restrict__ Bl,
    const float* __restrict__ bias, float* __restrict__ out,
    int NC16, int oss, int cho, int qlo, int qhi, float qscale)
{
    extern __shared__ char sm[];
    float4* As = (float4*)sm;                    // [st][ch][hl][128]
    uint2*  Bs = (uint2*)(sm + 8 * 128 * 16);    // [st][ch][hl][4][132]

    const int tid = threadIdx.x, lane = tid & 31, warp = tid >> 5;
    const int wm = warp >> 2, wn = warp & 3, gid = lane >> 2, tig4 = lane & 3;
    const int p0 = blockIdx.x * 128, mblk = blockIdx.y, img = blockIdx.z;
    const int NC32 = NC16 >> 1;

    const int aslot = tid & 127, hl = tid >> 7;
    const int btig = (tid >> 5) & 3, seg = tid & 31;
    const float4* Agl = (hl ? Al : Ah) + (size_t)mblk * NC16 * 128 + aslot;
    const uint2*  Bgl = (hl ? Bl : Bh) + ((size_t)img * NC16 * 4 + btig) * HW + p0 + seg * 4;

    float4 acc[2][4];
#pragma unroll
    for (int i = 0; i < 2; i++)
#pragma unroll
        for (int j = 0; j < 4; j++) acc[i][j] = make_float4(0.f, 0.f, 0.f, 0.f);

    float4 rA[2];
    uint4  rB[2][2];   // [ch][half]: covers 4 uint2 slots seg*4 .. seg*4+3

#define GLOAD(c)                                                            \
    {                                                                       \
        rA[0] = Agl[(size_t)(2 * (c)) * 128];                               \
        rA[1] = Agl[(size_t)(2 * (c) + 1) * 128];                           \
        rB[0][0] = *(const uint4*)(Bgl + (size_t)(2 * (c)) * 4 * HW);       \
        rB[0][1] = *(const uint4*)(Bgl + (size_t)(2 * (c)) * 4 * HW + 2);   \
        rB[1][0] = *(const uint4*)(Bgl + (size_t)(2 * (c) + 1) * 4 * HW);   \
        rB[1][1] = *(const uint4*)(Bgl + (size_t)(2 * (c) + 1) * 4 * HW + 2); \
    }
#define SSTORE(st)                                                          \
    {                                                                       \
        _Pragma("unroll")                                                   \
        for (int ch = 0; ch < 2; ch++) {                                    \
            As[(((st) * 2 + ch) * 2 + hl) * 128 + aslot] = rA[ch];          \
            uint2* bdst = &Bs[((((st) * 2 + ch) * 2 + hl) * 4 + btig) * 132 + seg * 4]; \
            *(uint4*)bdst       = rB[ch][0];                                \
            *(uint4*)(bdst + 2) = rB[ch][1];                                \
        }                                                                   \
    }

    GLOAD(0);
    SSTORE(0);
    __syncthreads();

    for (int c = 0; c < NC32; c++) {
        const bool more = (c + 1 < NC32);
        if (more) GLOAD(c + 1);

        const int st = c & 1;
#pragma unroll
        for (int ch = 0; ch < 2; ch++) {
            float4 A1f[2], A2f[2];
            A1f[0] = As[((st * 2 + ch) * 2 + 0) * 128 + (wm * 2 + 0) * 32 + lane];
            A1f[1] = As[((st * 2 + ch) * 2 + 0) * 128 + (wm * 2 + 1) * 32 + lane];
            A2f[0] = As[((st * 2 + ch) * 2 + 1) * 128 + (wm * 2 + 0) * 32 + lane];
            A2f[1] = As[((st * 2 + ch) * 2 + 1) * 128 + (wm * 2 + 1) * 32 + lane];
            uint2 B1f[4], B2f[4];
#pragma unroll
            for (int nt = 0; nt < 4; nt++) {
                int nn = wn * 32 + nt * 8 + gid;
                B1f[nt] = Bs[(((st * 2 + ch) * 2 + 0) * 4 + tig4) * 132 + nn];
                B2f[nt] = Bs[(((st * 2 + ch) * 2 + 1) * 4 + tig4) * 132 + nn];
            }
#pragma unroll
            for (int mt = 0; mt < 2; mt++) {
                uint32_t a10 = f2u(A1f[mt].x), a11 = f2u(A1f[mt].y),
                         a12 = f2u(A1f[mt].z), a13 = f2u(A1f[mt].w);
                uint32_t a20 = f2u(A2f[mt].x), a21 = f2u(A2f[mt].y),
                         a22 = f2u(A2f[mt].z), a23 = f2u(A2f[mt].w);
#pragma unroll
                for (int nt = 0; nt < 4; nt++) {
                    mmabf(acc[mt][nt], a10, a11, a12, a13, B1f[nt].x, B1f[nt].y);
                    mmabf(acc[mt][nt], a10, a11, a12, a13, B2f[nt].x, B2f[nt].y);
                    mmabf(acc[mt][nt], a20, a21, a22, a23, B1f[nt].x, B1f[nt].y);
                }
            }
        }
        if (more) SSTORE((c + 1) & 1);
        __syncthreads();
    }

    const int m0 = mblk * 64;
#pragma unroll
    for (int mt = 0; mt < 2; mt++) {
        int r0 = m0 + wm * 32 + mt * 16 + gid;
        int r1 = r0 + 8;
        float b0 = bias[r0], b1 = bias[r1];
        float s0 = (r0 >= qlo && r0 < qhi) ? qscale : 1.f;
        float s1 = (r1 >= qlo && r1 < qhi) ? qscale : 1.f;
#pragma unroll
        for (int nt = 0; nt < 4; nt++) {
            int c0 = p0 + wn * 32 + nt * 8 + tig4 * 2;
            float2 v0, v1;
            v0.x = (acc[mt][nt].x + b0) * s0;
            v0.y = (acc[mt][nt].y + b0) * s0;
            v1.x = (acc[mt][nt].z + b1) * s1;
            v1.y = (acc[mt][nt].w + b1) * s1;
            *(float2*)(out + (size_t)img * oss + (size_t)(cho + r0) * HW + c0) = v0;
            *(float2*)(out + (size_t)img * oss + (size_t)(cho + r1) * HW + c0) = v1;
        }
    }
}

// ---------------- fused rel-pos attention (unchanged, verified) ----------------
__global__ __launch_bounds__(128) void attn_kernel(
    const float* __restrict__ krw, const float* __restrict__ krh)
{
    __shared__ float srw[32][128];
    __shared__ float srh[32][128];
    __shared__ float Ks[16][64];
    __shared__ float Vs[16][64];

    const int tid = threadIdx.x;
    const int b = blockIdx.z, h = blockIdx.y;
    const int m = blockIdx.x * 128 + tid;

    const float* kb = g_kqv + ((size_t)b * 384 + h * DKH_) * HW;
    const float* qb = g_kqv + ((size_t)b * 384 + 128 + h * DKH_) * HW;
    const float* vb = g_kqv + ((size_t)b * 384 + 256 + h * DKH_) * HW;

    float q[16];
#pragma unroll
    for (int d = 0; d < 16; d++) q[d] = qb[(size_t)d * HW + m];

    const int xr = m >> 5, yc = m & 31;
#pragma unroll 1
    for (int j = 0; j < 32; j++) {
        const float* kw_ = krw + (j + 31 - yc) * DKH_;
        const float* kh_ = krh + (j + 31 - xr) * DKH_;
        float s1 = 0.f, s2 = 0.f;
#pragma unroll
        for (int d = 0; d < 16; d++) {
            s1 = fmaf(q[d], kw_[d], s1);
            s2 = fmaf(q[d], kh_[d], s2);
        }
        srw[j][tid] = s1;
        srh[j][tid] = s2;
    }

    float mrun = -1e30f, l = 0.f;
    float acc[16];
#pragma unroll
    for (int d = 0; d < 16; d++) acc[d] = 0.f;

    for (int n0 = 0; n0 < HW; n0 += 64) {
        __syncthreads();
#pragma unroll
        for (int r = 0; r < 8; r++) {
            int e = tid + r * 128;
            int d = e >> 6, nn = e & 63;
            Ks[d][nn] = kb[(size_t)d * HW + n0 + nn];
            Vs[d][nn] = vb[(size_t)d * HW + n0 + nn];
        }
        __syncthreads();

#pragma unroll 1
        for (int ii = 0; ii < 2; ii++) {
            const int i = (n0 >> 5) + ii;
            const float rh = srh[i][tid];
            float sbuf[32];
#pragma unroll
            for (int j = 0; j < 32; j++) sbuf[j] = srw[j][tid] + rh;

#pragma unroll
            for (int d = 0; d < 16; d++) {
                const float qd = q[d];
#pragma unroll
                for (int jb = 0; jb < 8; jb++) {
                    float4 k4 = *(const float4*)&Ks[d][ii * 32 + jb * 4];
                    sbuf[jb * 4 + 0] = fmaf(qd, k4.x, sbuf[jb * 4 + 0]);
                    sbuf[jb * 4 + 1] = fmaf(qd, k4.y, sbuf[jb * 4 + 1]);
                    sbuf[jb * 4 + 2] = fmaf(qd, k4.z, sbuf[jb * 4 + 2]);
                    sbuf[jb * 4 + 3] = fmaf(qd, k4.w, sbuf[jb * 4 + 3]);
                }
            }

            float cmax = -1e30f;
#pragma unroll
            for (int j = 0; j < 32; j++) cmax = fmaxf(cmax, sbuf[j]);
            float newm = fmaxf(mrun, cmax);
            float corr = exp2f((mrun - newm) * 1.44269504f);
            l *= corr;
#pragma unroll
            for (int d = 0; d < 16; d++) acc[d] *= corr;

#pragma unroll
            for (int j = 0; j < 32; j++) {
                float p = exp2f((sbuf[j] - newm) * 1.44269504f);
                l += p;
                sbuf[j] = p;
            }

#pragma unroll
            for (int d = 0; d < 16; d++) {
                float a = acc[d];
#pragma unroll
                for (int jb = 0; jb < 8; jb++) {
                    float4 v4 = *(const float4*)&Vs[d][ii * 32 + jb * 4];
                    a = fmaf(sbuf[jb * 4 + 0], v4.x, a);
                    a = fmaf(sbuf[jb * 4 + 1], v4.y, a);
                    a = fmaf(sbuf[jb * 4 + 2], v4.z, a);
                    a = fmaf(sbuf[jb * 4 + 3], v4.w, a);
                }
                acc[d] = a;
            }
            mrun = newm;
        }
    }

    const float inv = 1.f / l;
    float* o = g_attn + (((size_t)b * NHD + h) * HW + m) * 16;
#pragma unroll
    for (int t = 0; t < 4; t++) {
        float4 v;
        v.x = acc[t * 4 + 0] * inv;
        v.y = acc[t * 4 + 1] * inv;
        v.z = acc[t * 4 + 2] * inv;
        v.w = acc[t * 4 + 3] * inv;
        *(float4*)(o + t * 4) = v;
    }
}

// ---------------------------------------------------------------------------
extern "C" void kernel_launch(void* const* d_in, const int* in_sizes, int n_in,
                              void* d_out, int out_size)
{
    const float* x      = (const float*)d_in[0];
    const float* w_out  = (const float*)d_in[1];
    const float* b_out  = (const float*)d_in[2];
    const float* w_kqv  = (const float*)d_in[3];
    const float* b_kqv  = (const float*)d_in[4];
    const float* w_attn = (const float*)d_in[5];
    const float* b_attn = (const float*)d_in[6];
    const float* krw    = (const float*)d_in[7];
    const float* krh    = (const float*)d_in[8];
    float* out = (float*)d_out;

    float *kqv_p, *attn_p;
    float4 *A3h, *A3l, *Akh, *Akl, *Aph, *Apl;
    uint2 *B3h, *B3l, *Bkh, *Bkl, *Bph, *Bpl;
    cudaGetSymbolAddress((void**)&kqv_p, g_kqv);
    cudaGetSymbolAddress((void**)&attn_p, g_attn);
    cudaGetSymbolAddress((void**)&A3h, g_A3h); cudaGetSymbolAddress((void**)&A3l, g_A3l);
    cudaGetSymbolAddress((void**)&Akh, g_Akh); cudaGetSymbolAddress((void**)&Akl, g_Akl);
    cudaGetSymbolAddress((void**)&Aph, g_Aph); cudaGetSymbolAddress((void**)&Apl, g_Apl);
    cudaGetSymbolAddress((void**)&B3h, g_B3h); cudaGetSymbolAddress((void**)&B3l, g_B3l);
    cudaGetSymbolAddress((void**)&Bkh, g_Bkh); cudaGetSymbolAddress((void**)&Bkl, g_Bkl);
    cudaGetSymbolAddress((void**)&Bph, g_Bph); cudaGetSymbolAddress((void**)&Bpl, g_Bpl);

    static cudaStream_t s2 = nullptr;
    static cudaEvent_t ev_fork = nullptr, ev_join = nullptr;
    if (s2 == nullptr) {
        cudaStreamCreateWithFlags(&s2, cudaStreamNonBlocking);
        cudaEventCreateWithFlags(&ev_fork, cudaEventDisableTiming);
        cudaEventCreateWithFlags(&ev_join, cudaEventDisableTiming);
        cudaFuncSetAttribute(gemm_bf16,
                             cudaFuncAttributeMaxDynamicSharedMemorySize, GEMM_SMEM);
    }

    // fork: conv3x3 chain on side stream
    cudaEventRecord(ev_fork, 0);
    cudaStreamWaitEvent(s2, ev_fork, 0);
    xshift_kernel<<<dim3(256, 8), 256, 0, s2>>>(x);
    aprep_kernel<<<dim3(144, 6), 128, 0, s2>>>(w_out, A3h, A3l, 2304);
    bprep3_kernel<<<dim3(4, 144, 8), 256, 0, s2>>>(B3h, B3l);
    gemm_bf16<<<dim3(8, 6, 8), 256, GEMM_SMEM, s2>>>(
        A3h, A3l, B3h, B3l, b_out, out, 144, 512 * HW, 0, 0, 0, 1.f);
    cudaEventRecord(ev_join, s2);

    // main chain: kqv -> attention -> projection
    aprep_kernel<<<dim3(16, 6), 128>>>(w_kqv, Akh, Akl, 256);
    aprep_kernel<<<dim3(8, 2), 128>>>(w_attn, Aph, Apl, 128);
    bprep1_kernel<<<dim3(4, 16, 8), 256>>>(x, Bkh, Bkl, 256);
    gemm_bf16<<<dim3(8, 6, 8), 256, GEMM_SMEM>>>(
        Akh, Akl, Bkh, Bkl, b_kqv, kqv_p, 16, 384 * HW, 0, 128, 256, 0.25f);
    attn_kernel<<<dim3(8, 8, 8), 128>>>(krw, krh);
    bprep1_kernel<<<dim3(4, 8, 8), 256>>>(attn_p, Bph, Bpl, 128);
    gemm_bf16<<<dim3(8, 2, 8), 256, GEMM_SMEM>>>(
        Aph, Apl, Bph, Bpl, b_attn, out, 8, 512 * HW, 384, 0, 0, 1.f);

    // join
    cudaStreamWaitEvent(0, ev_join, 0);
}

// round 17
// speedup vs baseline: 2.1068x; 1.0060x over previous
#include <cuda_runtime.h>
#include <cstdint>

#define NB   8
#define HH   32
#define WW   32
#define HW   1024
#define NHD  8
#define DKH_ 16
#define HWP  1088   // 34*32 padded rows

typedef unsigned long long ull;

// ---------------- scratch (no cudaMalloc allowed) ----------------
__device__ float g_kqv[(size_t)NB * 384 * HW];
__device__ float g_attn[(size_t)NB * 128 * HW];
__device__ float g_xs[(size_t)NB * 3 * 256 * HWP];          // [img][kw][ci][34][32]
__device__ uint2 g_B3h[(size_t)NB * 144 * 4 * HW];          // [img][c16][tig][pix]
__device__ uint2 g_B3l[(size_t)NB * 144 * 4 * HW];
__device__ uint2 g_Bkh[(size_t)NB * 16 * 4 * HW];
__device__ uint2 g_Bkl[(size_t)NB * 16 * 4 * HW];
__device__ uint2 g_Bph[(size_t)NB * 8 * 4 * HW];
__device__ uint2 g_Bpl[(size_t)NB * 8 * 4 * HW];
__device__ float4 g_A3h[6 * 144 * 128], g_A3l[6 * 144 * 128];
__device__ float4 g_Akh[6 * 16 * 128],  g_Akl[6 * 16 * 128];
__device__ float4 g_Aph[2 * 8 * 128],   g_Apl[2 * 8 * 128];

// ---------------- bf16x3 split helpers ----------------
__device__ __forceinline__ uint32_t bfhi(float v) {
    uint32_t u = __float_as_uint(v);
    return (u + 0x7FFFu + ((u >> 16) & 1u)) & 0xFFFF0000u;
}
__device__ __forceinline__ uint32_t packlo(float l0, float l1) {
    uint32_t r;
    asm("cvt.rn.bf16x2.f32 %0, %1, %2;" : "=r"(r) : "f"(l1), "f"(l0));
    return r;
}
__device__ __forceinline__ uint32_t f2u(float x) { return __float_as_uint(x); }
__device__ __forceinline__ float    u2f(uint32_t x) { return __uint_as_float(x); }

__device__ __forceinline__ void pack4(float a, float b, float c, float d,
                                      uint2& hi, uint2& lo) {
    uint32_t ha = bfhi(a), hb = bfhi(b), hc = bfhi(c), hd = bfhi(d);
    hi.x = __byte_perm(ha, hb, 0x7632);
    hi.y = __byte_perm(hc, hd, 0x7632);
    lo.x = packlo(a - u2f(ha), b - u2f(hb));
    lo.y = packlo(c - u2f(hc), d - u2f(hd));
}

__device__ __forceinline__ void mmabf(float4& d,
                                      uint32_t a0, uint32_t a1, uint32_t a2, uint32_t a3,
                                      uint32_t b0, uint32_t b1) {
    asm volatile(
        "mma.sync.aligned.m16n8k16.row.col.f32.bf16.bf16.f32 "
        "{%0,%1,%2,%3},{%4,%5,%6,%7},{%8,%9},{%0,%1,%2,%3};"
        : "+f"(d.x), "+f"(d.y), "+f"(d.z), "+f"(d.w)
        : "r"(a0), "r"(a1), "r"(a2), "r"(a3), "r"(b0), "r"(b1));
}

// ---------------- f32x2 helpers (B300 dual-lane FP32) ----------------
__device__ __forceinline__ ull pk2(float lo, float hi) {
    ull r; asm("mov.b64 %0, {%1, %2};" : "=l"(r) : "f"(lo), "f"(hi)); return r;
}
__device__ __forceinline__ void upk2(ull v, float& lo, float& hi) {
    asm("mov.b64 {%0, %1}, %2;" : "=f"(lo), "=f"(hi) : "l"(v));
}
__device__ __forceinline__ ull fma2(ull a, ull b, ull c) {
    ull d; asm("fma.rn.f32x2 %0, %1, %2, %3;" : "=l"(d) : "l"(a), "l"(b), "l"(c)); return d;
}
__device__ __forceinline__ ull add2(ull a, ull b) {
    ull d; asm("add.rn.f32x2 %0, %1, %2;" : "=l"(d) : "l"(a), "l"(b)); return d;
}
__device__ __forceinline__ ull mul2(ull a, ull b) {
    ull d; asm("mul.rn.f32x2 %0, %1, %2;" : "=l"(d) : "l"(a), "l"(b)); return d;
}
__device__ __forceinline__ float ex2f(float x) {
    float r; asm("ex2.approx.ftz.f32 %0, %1;" : "=f"(r) : "f"(x)); return r;
}

// ---------------- prepass: shifted, padded x copies ----------------
__global__ __launch_bounds__(256) void xshift_kernel(const float* __restrict__ x)
{
    __shared__ float s[1024];
    const int ci = blockIdx.x, img = blockIdx.y, tid = threadIdx.x;
    const float* src = x + ((size_t)img * 256 + ci) * HW;
    ((float4*)s)[tid] = ((const float4*)src)[tid];
    __syncthreads();
    for (int idx = tid; idx < 3 * HWP; idx += 256) {
        int kw = idx / HWP, rem = idx - kw * HWP;
        int r = rem >> 5, w = rem & 31;
        int h = r - 1, wp = w + kw - 1;
        float v = ((unsigned)h < HH && (unsigned)wp < WW) ? s[h * 32 + wp] : 0.f;
        g_xs[((size_t)(img * 3 + kw) * 256 + ci) * HWP + rem] = v;
    }
}

// ---------------- prepass: weights -> fragment layout ----------------
__global__ __launch_bounds__(128) void aprep_kernel(
    const float* __restrict__ W, float4* __restrict__ Ah, float4* __restrict__ Al,
    int Ktot)
{
    const int c16 = blockIdx.x, mblk = blockIdx.y, slot = threadIdx.x;
    const int awm = slot >> 6, amt = (slot >> 5) & 1, aln = slot & 31;
    const int agid = aln >> 2, atig = aln & 3;
    const int r0 = mblk * 64 + awm * 32 + amt * 16 + agid;
    const int k0 = c16 * 16 + 2 * atig;
    const float* w0 = W + (size_t)r0 * Ktot + k0;
    const float* w1 = W + (size_t)(r0 + 8) * Ktot + k0;
    float2 a = *(const float2*)w0,       b = *(const float2*)w1;
    float2 c = *(const float2*)(w0 + 8), d = *(const float2*)(w1 + 8);
    uint2 h0, l0, h1, l1;
    pack4(a.x, a.y, b.x, b.y, h0, l0);
    pack4(c.x, c.y, d.x, d.y, h1, l1);
    const int o = (mblk * gridDim.x + c16) * 128 + slot;
    Ah[o] = make_float4(u2f(h0.x), u2f(h0.y), u2f(h1.x), u2f(h1.y));
    Al[o] = make_float4(u2f(l0.x), u2f(l0.y), u2f(l1.x), u2f(l1.y));
}

// ---------------- prepass: 1x1 operand (direct channel reads) ----------------
__global__ __launch_bounds__(256) void bprep1_kernel(
    const float* __restrict__ src, uint2* __restrict__ Bh, uint2* __restrict__ Bl,
    int Cin)
{
    const int tig = blockIdx.x, c16 = blockIdx.y, img = blockIdx.z;
    const int n0 = threadIdx.x * 4;
    const int kb = c16 * 16 + 2 * tig;
    const float* base = src + (size_t)img * Cin * HW + n0;
    float4 v0 = *(const float4*)(base + (size_t)(kb    ) * HW);
    float4 v1 = *(const float4*)(base + (size_t)(kb + 1) * HW);
    float4 v2 = *(const float4*)(base + (size_t)(kb + 8) * HW);
    float4 v3 = *(const float4*)(base + (size_t)(kb + 9) * HW);
    const float *p0 = (const float*)&v0, *p1 = (const float*)&v1;
    const float *p2 = (const float*)&v2, *p3 = (const float*)&v3;
    uint2 h[4], l[4];
#pragma unroll
    for (int e = 0; e < 4; e++) pack4(p0[e], p1[e], p2[e], p3[e], h[e], l[e]);
    size_t o = (((size_t)img * gridDim.y + c16) * 4 + tig) * HW + n0;
    *(uint4*)&Bh[o]     = *(uint4*)&h[0];
    *(uint4*)&Bh[o + 2] = *(uint4*)&h[2];
    *(uint4*)&Bl[o]     = *(uint4*)&l[0];
    *(uint4*)&Bl[o + 2] = *(uint4*)&l[2];
}

// ---------------- prepass: 3x3 im2col operand (from g_xs) ----------------
__global__ __launch_bounds__(256) void bprep3_kernel(
    uint2* __restrict__ Bh, uint2* __restrict__ Bl)
{
    const int tig = blockIdx.x, c16 = blockIdx.y, img = blockIdx.z;
    const int n0 = threadIdx.x * 4;
    const int ph = n0 >> 5, w0 = n0 & 31;
    const int kb = c16 * 16 + 2 * tig;
    const int ks[4] = {kb, kb + 1, kb + 8, kb + 9};
    float4 v[4];
#pragma unroll
    for (int j = 0; j < 4; j++) {
        int k = ks[j];
        unsigned ci = (unsigned)k / 9u, rr = (unsigned)k - 9u * ci;
        int kh = (rr >= 6) ? 2 : ((rr >= 3) ? 1 : 0);
        int kw = (int)rr - 3 * kh;
        v[j] = *(const float4*)(g_xs + ((size_t)(img * 3 + kw) * 256 + ci) * HWP
                                + (ph + kh) * 32 + w0);
    }
    const float *p0 = (const float*)&v[0], *p1 = (const float*)&v[1];
    const float *p2 = (const float*)&v[2], *p3 = (const float*)&v[3];
    uint2 h[4], l[4];
#pragma unroll
    for (int e = 0; e < 4; e++) pack4(p0[e], p1[e], p2[e], p3[e], h[e], l[e]);
    size_t o = (((size_t)img * 144 + c16) * 4 + tig) * HW + n0;
    *(uint4*)&Bh[o]     = *(uint4*)&h[0];
    *(uint4*)&Bh[o + 2] = *(uint4*)&h[2];
    *(uint4*)&Bl[o]     = *(uint4*)&l[0];
    *(uint4*)&Bl[o + 2] = *(uint4*)&l[2];
}

// ---------------- lean bf16x3 GEMM: BK=32, double-buffered ----------------
#define GEMM_SMEM (8 * 128 * 16 + 8 * 4 * 132 * 8)   // 50176 B

__global__ __launch_bounds__(256, 2) void gemm_bf16(
    const float4* __restrict__ Ah, const float4* __restrict__ Al,
    const uint2* __restrict__ Bh, const uint2* __restrict__ Bl,
    const float* __restrict__ bias, float* __restrict__ out,
    int NC16, int oss, int cho, int qlo, int qhi, float qscale)
{
    extern __shared__ char sm[];
    float4* As = (float4*)sm;                    // [st][ch][hl][128]
    uint2*  Bs = (uint2*)(sm + 8 * 128 * 16);    // [st][ch][hl][4][132]

    const int tid = threadIdx.x, lane = tid & 31, warp = tid >> 5;
    const int wm = warp >> 2, wn = warp & 3, gid = lane >> 2, tig4 = lane & 3;
    const int p0 = blockIdx.x * 128, mblk = blockIdx.y, img = blockIdx.z;
    const int NC32 = NC16 >> 1;

    const int aslot = tid & 127, hl = tid >> 7;
    const int btig = (tid >> 5) & 3, seg = tid & 31;
    const float4* Agl = (hl ? Al : Ah) + (size_t)mblk * NC16 * 128 + aslot;
    const uint2*  Bgl = (hl ? Bl : Bh) + ((size_t)img * NC16 * 4 + btig) * HW + p0 + seg * 4;

    float4 acc[2][4];
#pragma unroll
    for (int i = 0; i < 2; i++)
#pragma unroll
        for (int j = 0; j < 4; j++) acc[i][j] = make_float4(0.f, 0.f, 0.f, 0.f);

    float4 rA[2];
    uint4  rB[2][2];   // [ch][half]: covers 4 uint2 slots seg*4 .. seg*4+3

#define GLOAD(c)                                                            \
    {                                                                       \
        rA[0] = Agl[(size_t)(2 * (c)) * 128];                               \
        rA[1] = Agl[(size_t)(2 * (c) + 1) * 128];                           \
        rB[0][0] = *(const uint4*)(Bgl + (size_t)(2 * (c)) * 4 * HW);       \
        rB[0][1] = *(const uint4*)(Bgl + (size_t)(2 * (c)) * 4 * HW + 2);   \
        rB[1][0] = *(const uint4*)(Bgl + (size_t)(2 * (c) + 1) * 4 * HW);   \
        rB[1][1] = *(const uint4*)(Bgl + (size_t)(2 * (c) + 1) * 4 * HW + 2); \
    }
#define SSTORE(st)                                                          \
    {                                                                       \
        _Pragma("unroll")                                                   \
        for (int ch = 0; ch < 2; ch++) {                                    \
            As[(((st) * 2 + ch) * 2 + hl) * 128 + aslot] = rA[ch];          \
            uint2* bdst = &Bs[((((st) * 2 + ch) * 2 + hl) * 4 + btig) * 132 + seg * 4]; \
            *(uint4*)bdst       = rB[ch][0];                                \
            *(uint4*)(bdst + 2) = rB[ch][1];                                \
        }                                                                   \
    }

    GLOAD(0);
    SSTORE(0);
    __syncthreads();

    for (int c = 0; c < NC32; c++) {
        const bool more = (c + 1 < NC32);
        if (more) GLOAD(c + 1);

        const int st = c & 1;
#pragma unroll
        for (int ch = 0; ch < 2; ch++) {
            float4 A1f[2], A2f[2];
            A1f[0] = As[((st * 2 + ch) * 2 + 0) * 128 + (wm * 2 + 0) * 32 + lane];
            A1f[1] = As[((st * 2 + ch) * 2 + 0) * 128 + (wm * 2 + 1) * 32 + lane];
            A2f[0] = As[((st * 2 + ch) * 2 + 1) * 128 + (wm * 2 + 0) * 32 + lane];
            A2f[1] = As[((st * 2 + ch) * 2 + 1) * 128 + (wm * 2 + 1) * 32 + lane];
            uint2 B1f[4], B2f[4];
#pragma unroll
            for (int nt = 0; nt < 4; nt++) {
                int nn = wn * 32 + nt * 8 + gid;
                B1f[nt] = Bs[(((st * 2 + ch) * 2 + 0) * 4 + tig4) * 132 + nn];
                B2f[nt] = Bs[(((st * 2 + ch) * 2 + 1) * 4 + tig4) * 132 + nn];
            }
#pragma unroll
            for (int mt = 0; mt < 2; mt++) {
                uint32_t a10 = f2u(A1f[mt].x), a11 = f2u(A1f[mt].y),
                         a12 = f2u(A1f[mt].z), a13 = f2u(A1f[mt].w);
                uint32_t a20 = f2u(A2f[mt].x), a21 = f2u(A2f[mt].y),
                         a22 = f2u(A2f[mt].z), a23 = f2u(A2f[mt].w);
#pragma unroll
                for (int nt = 0; nt < 4; nt++) {
                    mmabf(acc[mt][nt], a10, a11, a12, a13, B1f[nt].x, B1f[nt].y);
                    mmabf(acc[mt][nt], a10, a11, a12, a13, B2f[nt].x, B2f[nt].y);
                    mmabf(acc[mt][nt], a20, a21, a22, a23, B1f[nt].x, B1f[nt].y);
                }
            }
        }
        if (more) SSTORE((c + 1) & 1);
        __syncthreads();
    }

    const int m0 = mblk * 64;
#pragma unroll
    for (int mt = 0; mt < 2; mt++) {
        int r0 = m0 + wm * 32 + mt * 16 + gid;
        int r1 = r0 + 8;
        float b0 = bias[r0], b1 = bias[r1];
        float s0 = (r0 >= qlo && r0 < qhi) ? qscale : 1.f;
        float s1 = (r1 >= qlo && r1 < qhi) ? qscale : 1.f;
#pragma unroll
        for (int nt = 0; nt < 4; nt++) {
            int c0 = p0 + wn * 32 + nt * 8 + tig4 * 2;
            float2 v0, v1;
            v0.x = (acc[mt][nt].x + b0) * s0;
            v0.y = (acc[mt][nt].y + b0) * s0;
            v1.x = (acc[mt][nt].z + b1) * s1;
            v1.y = (acc[mt][nt].w + b1) * s1;
            *(float2*)(out + (size_t)img * oss + (size_t)(cho + r0) * HW + c0) = v0;
            *(float2*)(out + (size_t)img * oss + (size_t)(cho + r1) * HW + c0) = v1;
        }
    }
}

// ---------------- fused rel-pos attention, f32x2 (FFMA2) version ----------------
// bias(m=(x,y), n=(i,j)) = q_m.krw[j-y+31] + q_m.krh[i-x+31]
// Thread = query row m. All hot FMAs packed 2-wide on the B300 dual FP32 pipe.
__global__ __launch_bounds__(128, 4) void attn_kernel(
    const float* __restrict__ krw, const float* __restrict__ krh)
{
    __shared__ ull   srw2[16][128];  // {srw[2j],srw[2j+1]} per thread
    __shared__ float srh[32][128];
    __shared__ float Ks[16][64];
    __shared__ ull   Vs2[8][64];     // {V[2d][n],V[2d+1][n]}

    const int tid = threadIdx.x;
    const int b = blockIdx.z, h = blockIdx.y;
    const int m = blockIdx.x * 128 + tid;

    const float* kb = g_kqv + ((size_t)b * 384 + h * DKH_) * HW;
    const float* qb = g_kqv + ((size_t)b * 384 + 128 + h * DKH_) * HW;
    const float* vb = g_kqv + ((size_t)b * 384 + 256 + h * DKH_) * HW;

    float q[16];
#pragma unroll
    for (int d = 0; d < 16; d++) q[d] = qb[(size_t)d * HW + m];

    // preamble: rel logits via adjacent-packed q
    {
        ull qp[8];
#pragma unroll
        for (int d2 = 0; d2 < 8; d2++) qp[d2] = pk2(q[2 * d2], q[2 * d2 + 1]);
        const int xr = m >> 5, yc = m & 31;
        float s1prev = 0.f;
#pragma unroll 1
        for (int j = 0; j < 32; j++) {
            const float* kw_ = krw + (j + 31 - yc) * DKH_;
            const float* kh_ = krh + (j + 31 - xr) * DKH_;
            ull a1 = 0ull, a2 = 0ull;
#pragma unroll
            for (int d2 = 0; d2 < 8; d2++) {
                a1 = fma2(qp[d2], *(const ull*)(kw_ + 2 * d2), a1);
                a2 = fma2(qp[d2], *(const ull*)(kh_ + 2 * d2), a2);
            }
            float l1, h1, l2v, h2v;
            upk2(a1, l1, h1);
            upk2(a2, l2v, h2v);
            float s1 = l1 + h1;
            srh[j][tid] = l2v + h2v;
            if (j & 1) srw2[j >> 1][tid] = pk2(s1prev, s1);
            else       s1prev = s1;
        }
    }

    float mrun = -1e30f;
    ull l2 = 0ull;
    ull acc2[8];
#pragma unroll
    for (int d2 = 0; d2 < 8; d2++) acc2[d2] = 0ull;

    for (int n0 = 0; n0 < HW; n0 += 64) {
        __syncthreads();
#pragma unroll
        for (int r = 0; r < 8; r++) {
            int e = tid + r * 128;
            int d = e >> 6, nn = e & 63;
            Ks[d][nn] = kb[(size_t)d * HW + n0 + nn];
        }
#pragma unroll
        for (int r = 0; r < 4; r++) {
            int e = tid + r * 128;
            int d2 = e >> 6, nn = e & 63;
            Vs2[d2][nn] = pk2(vb[(size_t)(2 * d2) * HW + n0 + nn],
                              vb[(size_t)(2 * d2 + 1) * HW + n0 + nn]);
        }
        __syncthreads();

#pragma unroll 1
        for (int ii = 0; ii < 2; ii++) {
            const int i = (n0 >> 5) + ii;
            const float rh = srh[i][tid];
            const ull rh2 = pk2(rh, rh);
            ull sb2[16];
#pragma unroll
            for (int j2 = 0; j2 < 16; j2++) sb2[j2] = add2(srw2[j2][tid], rh2);

            // QK: dup-packed q x uniform K pairs
#pragma unroll
            for (int d = 0; d < 16; d++) {
                const ull qd2 = pk2(q[d], q[d]);
                const ulonglong2* kp = (const ulonglong2*)&Ks[d][ii * 32];
#pragma unroll
                for (int j4 = 0; j4 < 8; j4++) {
                    ulonglong2 kv = kp[j4];
                    sb2[2 * j4]     = fma2(qd2, kv.x, sb2[2 * j4]);
                    sb2[2 * j4 + 1] = fma2(qd2, kv.y, sb2[2 * j4 + 1]);
                }
            }

            float sb[32];
#pragma unroll
            for (int j2 = 0; j2 < 16; j2++) upk2(sb2[j2], sb[2 * j2], sb[2 * j2 + 1]);
            float cmax = sb[0];
#pragma unroll
            for (int j = 1; j < 32; j++) cmax = fmaxf(cmax, sb[j]);
            float newm = fmaxf(mrun, cmax);
            float corr = ex2f((mrun - newm) * 1.44269504f);
            ull corr2 = pk2(corr, corr);
            l2 = mul2(l2, corr2);
#pragma unroll
            for (int d2 = 0; d2 < 8; d2++) acc2[d2] = mul2(acc2[d2], corr2);

            const float cc = -newm * 1.44269504f;
#pragma unroll
            for (int jb = 0; jb < 4; jb++) {
                ull pp[8];
#pragma unroll
                for (int jj = 0; jj < 8; jj++) {
                    float p = ex2f(fmaf(sb[jb * 8 + jj], 1.44269504f, cc));
                    pp[jj] = pk2(p, p);
                    l2 = add2(l2, pp[jj]);
                }
#pragma unroll
                for (int d2 = 0; d2 < 8; d2++) {
                    const ulonglong2* vp =
                        (const ulonglong2*)&Vs2[d2][ii * 32 + jb * 8];
                    ulonglong2 v01 = vp[0], v23 = vp[1], v45 = vp[2], v67 = vp[3];
                    ull a = acc2[d2];
                    a = fma2(pp[0], v01.x, a);
                    a = fma2(pp[1], v01.y, a);
                    a = fma2(pp[2], v23.x, a);
                    a = fma2(pp[3], v23.y, a);
                    a = fma2(pp[4], v45.x, a);
                    a = fma2(pp[5], v45.y, a);
                    a = fma2(pp[6], v67.x, a);
                    a = fma2(pp[7], v67.y, a);
                    acc2[d2] = a;
                }
            }
            mrun = newm;
        }
    }

    float llo, lhi;
    upk2(l2, llo, lhi);
    const float inv = 1.f / llo;
    const ull inv2 = pk2(inv, inv);
    ull* o = (ull*)(g_attn + (((size_t)b * NHD + h) * HW + m) * 16);
#pragma unroll
    for (int d2 = 0; d2 < 8; d2++) o[d2] = mul2(acc2[d2], inv2);
}

// ---------------------------------------------------------------------------
extern "C" void kernel_launch(void* const* d_in, const int* in_sizes, int n_in,
                              void* d_out, int out_size)
{
    const float* x      = (const float*)d_in[0];
    const float* w_out  = (const float*)d_in[1];
    const float* b_out  = (const float*)d_in[2];
    const float* w_kqv  = (const float*)d_in[3];
    const float* b_kqv  = (const float*)d_in[4];
    const float* w_attn = (const float*)d_in[5];
    const float* b_attn = (const float*)d_in[6];
    const float* krw    = (const float*)d_in[7];
    const float* krh    = (const float*)d_in[8];
    float* out = (float*)d_out;

    float *kqv_p, *attn_p;
    float4 *A3h, *A3l, *Akh, *Akl, *Aph, *Apl;
    uint2 *B3h, *B3l, *Bkh, *Bkl, *Bph, *Bpl;
    cudaGetSymbolAddress((void**)&kqv_p, g_kqv);
    cudaGetSymbolAddress((void**)&attn_p, g_attn);
    cudaGetSymbolAddress((void**)&A3h, g_A3h); cudaGetSymbolAddress((void**)&A3l, g_A3l);
    cudaGetSymbolAddress((void**)&Akh, g_Akh); cudaGetSymbolAddress((void**)&Akl, g_Akl);
    cudaGetSymbolAddress((void**)&Aph, g_Aph); cudaGetSymbolAddress((void**)&Apl, g_Apl);
    cudaGetSymbolAddress((void**)&B3h, g_B3h); cudaGetSymbolAddress((void**)&B3l, g_B3l);
    cudaGetSymbolAddress((void**)&Bkh, g_Bkh); cudaGetSymbolAddress((void**)&Bkl, g_Bkl);
    cudaGetSymbolAddress((void**)&Bph, g_Bph); cudaGetSymbolAddress((void**)&Bpl, g_Bpl);

    static cudaStream_t s2 = nullptr;
    static cudaEvent_t ev_fork = nullptr, ev_join = nullptr;
    if (s2 == nullptr) {
        cudaStreamCreateWithFlags(&s2, cudaStreamNonBlocking);
        cudaEventCreateWithFlags(&ev_fork, cudaEventDisableTiming);
        cudaEventCreateWithFlags(&ev_join, cudaEventDisableTiming);
        cudaFuncSetAttribute(gemm_bf16,
                             cudaFuncAttributeMaxDynamicSharedMemorySize, GEMM_SMEM);
    }

    // fork: conv3x3 chain on side stream
    cudaEventRecord(ev_fork, 0);
    cudaStreamWaitEvent(s2, ev_fork, 0);
    xshift_kernel<<<dim3(256, 8), 256, 0, s2>>>(x);
    aprep_kernel<<<dim3(144, 6), 128, 0, s2>>>(w_out, A3h, A3l, 2304);
    bprep3_kernel<<<dim3(4, 144, 8), 256, 0, s2>>>(B3h, B3l);
    gemm_bf16<<<dim3(8, 6, 8), 256, GEMM_SMEM, s2>>>(
        A3h, A3l, B3h, B3l, b_out, out, 144, 512 * HW, 0, 0, 0, 1.f);
    cudaEventRecord(ev_join, s2);

    // main chain: kqv -> attention -> projection
    aprep_kernel<<<dim3(16, 6), 128>>>(w_kqv, Akh, Akl, 256);
    aprep_kernel<<<dim3(8, 2), 128>>>(w_attn, Aph, Apl, 128);
    bprep1_kernel<<<dim3(4, 16, 8), 256>>>(x, Bkh, Bkl, 256);
    gemm_bf16<<<dim3(8, 6, 8), 256, GEMM_SMEM>>>(
        Akh, Akl, Bkh, Bkl, b_kqv, kqv_p, 16, 384 * HW, 0, 128, 256, 0.25f);
    attn_kernel<<<dim3(8, 8, 8), 128>>>(krw, krh);
    bprep1_kernel<<<dim3(4, 8, 8), 256>>>(attn_p, Bph, Bpl, 128);
    gemm_bf16<<<dim3(8, 2, 8), 256, GEMM_SMEM>>>(
        Aph, Apl, Bph, Bpl, b_attn, out, 8, 512 * HW, 384, 0, 0, 1.f);

    // join
    cudaStreamWaitEvent(0, ev_join, 0);
}